// round 3
// baseline (speedup 1.0000x reference)
#include <cuda_runtime.h>
#include <math.h>

#define NN      50000
#define INDIM   512
#define HID     256
#define CC      8
#define E2C     400000
#define EEC     800000
#define T_ITERS 10
#define ETA_C   0.2f
#define W_MAXC  0.8f
#define ALPHA_MAXC 1.5f
#define EPS_C   1e-12f

// ------------------- scratch (device globals; no allocation allowed) ---------
__device__ __align__(16) float g_h[NN * HID];        // 51.2 MB
__device__ __align__(16) float g_logphi[NN * CC];
__device__ __align__(16) float g_deg[NN];
__device__ __align__(16) float g_w[E2C];
__device__ __align__(16) float g_en[E2C];
__device__ __align__(16) float g_K[(size_t)E2C * 64]; // 102.4 MB
__device__ __align__(16) float g_m[EEC * CC];        // 25.6 MB
__device__ __align__(16) float g_lf[EEC * CC];       // 25.6 MB
__device__ __align__(16) float g_sumA[NN * CC];
__device__ __align__(16) float g_sumB[NN * CC];
__device__ __align__(16) float g_Rs[64];
__device__ float g_alpha;

// ------------------- packed f32x2 FMA ----------------------------------------
union F2 { float2 f; unsigned long long u; };

__device__ __forceinline__ void ffma2(F2& d, const F2& a, const F2& b) {
    asm("fma.rn.f32x2 %0, %1, %2, %0;" : "+l"(d.u) : "l"(a.u), "l"(b.u));
}
__device__ __forceinline__ F2 bcast2(float v) {
    F2 r; r.f = make_float2(v, v); return r;
}

// ------------------- vector reduction (atomic add, no return) -----------------
__device__ __forceinline__ void red4(float* p, float a, float b, float c, float d) {
    asm volatile("red.global.add.v4.f32 [%0], {%1, %2, %3, %4};"
                 :: "l"(p), "f"(a), "f"(b), "f"(c), "f"(d) : "memory");
}

// ------------------- generic zero --------------------------------------------
__global__ void zero4_k(float4* __restrict__ p, int n4) {
    int i = blockIdx.x * blockDim.x + threadIdx.x;
    if (i < n4) p[i] = make_float4(0.f, 0.f, 0.f, 0.f);
}

// ------------------- prep: zero deg + symmetrized R + alpha -------------------
__global__ void prep0_k(const float* __restrict__ R_raw,
                        const float* __restrict__ rsl,
                        const float* __restrict__ msg) {
    int i = blockIdx.x * blockDim.x + threadIdx.x;
    if (i < NN) g_deg[i] = 0.f;
    if (blockIdx.x == 0) {
        int t = threadIdx.x;
        if (t == 0) g_alpha = ALPHA_MAXC / (1.f + expf(-msg[0]));
        if (t < 64) {
            int c = t >> 3, d = t & 7;
            float r = 0.5f * (R_raw[c * 8 + d] + R_raw[d * 8 + c]);
            float xr = rsl[0];
            float sp = (xr > 20.f) ? xr : log1pf(expf(xr));
            g_Rs[t] = (sp + 1e-6f) * tanhf(r);
        }
    }
}

// ------------------- encoder GEMM: h = relu(x @ W1 + b1) ---------------------
__global__ __launch_bounds__(256) void enc_gemm_k(const float* __restrict__ X,
                                                  const float* __restrict__ W,
                                                  const float* __restrict__ B) {
    __shared__ float Xs[16][138];
    __shared__ float Ws[16][64];
    int tid = threadIdx.x;
    int tx = tid & 15, ty = tid >> 4;
    int row0 = blockIdx.x * 128;
    int col0 = blockIdx.y * 64;
    F2 acc[4][4];
#pragma unroll
    for (int jp = 0; jp < 4; jp++)
#pragma unroll
        for (int u = 0; u < 4; u++) acc[jp][u].f = make_float2(0.f, 0.f);

    for (int k0 = 0; k0 < INDIM; k0 += 16) {
#pragma unroll
        for (int i = 0; i < 2; i++) {
            int m = (tid >> 2) + i * 64;
            int k4 = (tid & 3) * 4;
            int gr = row0 + m;
            float4 v = make_float4(0.f, 0.f, 0.f, 0.f);
            if (gr < NN) v = *(const float4*)(X + (size_t)gr * INDIM + k0 + k4);
            Xs[k4 + 0][m] = v.x; Xs[k4 + 1][m] = v.y;
            Xs[k4 + 2][m] = v.z; Xs[k4 + 3][m] = v.w;
        }
        {
            int k = tid >> 4;
            int c4 = (tid & 15) * 4;
            *(float4*)&Ws[k][c4] = *(const float4*)(W + (size_t)(k0 + k) * HID + col0 + c4);
        }
        __syncthreads();
#pragma unroll
        for (int kk = 0; kk < 16; kk++) {
            F2 a2[4];
#pragma unroll
            for (int jp = 0; jp < 4; jp++)
                a2[jp].f = *(const float2*)&Xs[kk][ty * 8 + jp * 2];
            float4 w4 = *(const float4*)&Ws[kk][tx * 4];
            F2 wp[4] = {bcast2(w4.x), bcast2(w4.y), bcast2(w4.z), bcast2(w4.w)};
#pragma unroll
            for (int jp = 0; jp < 4; jp++)
#pragma unroll
                for (int u = 0; u < 4; u++)
                    ffma2(acc[jp][u], a2[jp], wp[u]);
        }
        __syncthreads();
    }
    float4 b4 = *(const float4*)(B + col0 + tx * 4);
#pragma unroll
    for (int jp = 0; jp < 4; jp++) {
#pragma unroll
        for (int h = 0; h < 2; h++) {
            int gr = row0 + ty * 8 + jp * 2 + h;
            if (gr < NN) {
                float4 o;
                float v0 = h ? acc[jp][0].f.y : acc[jp][0].f.x;
                float v1 = h ? acc[jp][1].f.y : acc[jp][1].f.x;
                float v2 = h ? acc[jp][2].f.y : acc[jp][2].f.x;
                float v3 = h ? acc[jp][3].f.y : acc[jp][3].f.x;
                o.x = fmaxf(v0 + b4.x, 0.f);
                o.y = fmaxf(v1 + b4.y, 0.f);
                o.z = fmaxf(v2 + b4.z, 0.f);
                o.w = fmaxf(v3 + b4.w, 0.f);
                *(float4*)(g_h + (size_t)gr * HID + col0 + tx * 4) = o;
            }
        }
    }
}

// ------------------- logits + log_softmax: one warp per node ------------------
__global__ void logits_k(const float* __restrict__ W2, const float* __restrict__ B2) {
    int gt = blockIdx.x * blockDim.x + threadIdx.x;
    int node = gt >> 5, lane = gt & 31;
    if (node >= NN) return;
    const float* hrow = g_h + (size_t)node * HID;
    float acc[8];
#pragma unroll
    for (int c = 0; c < 8; c++) acc[c] = 0.f;
    for (int j = lane; j < HID; j += 32) {
        float hv = hrow[j];
        float4 wA = *(const float4*)(W2 + j * 8);
        float4 wB = *(const float4*)(W2 + j * 8 + 4);
        acc[0] += hv * wA.x; acc[1] += hv * wA.y;
        acc[2] += hv * wA.z; acc[3] += hv * wA.w;
        acc[4] += hv * wB.x; acc[5] += hv * wB.y;
        acc[6] += hv * wB.z; acc[7] += hv * wB.w;
    }
#pragma unroll
    for (int c = 0; c < 8; c++)
#pragma unroll
        for (int off = 16; off; off >>= 1)
            acc[c] += __shfl_xor_sync(0xffffffffu, acc[c], off);
    if (lane == 0) {
        float lg[8], mx = -1e30f;
#pragma unroll
        for (int c = 0; c < 8; c++) { lg[c] = acc[c] + B2[c]; mx = fmaxf(mx, lg[c]); }
        float s = 0.f;
#pragma unroll
        for (int c = 0; c < 8; c++) s += expf(lg[c] - mx);
        float lse = mx + logf(s);
        *(float4*)(g_logphi + node * 8)     = make_float4(lg[0]-lse, lg[1]-lse, lg[2]-lse, lg[3]-lse);
        *(float4*)(g_logphi + node * 8 + 4) = make_float4(lg[4]-lse, lg[5]-lse, lg[6]-lse, lg[7]-lse);
    }
}

// ------------------- degrees -------------------------------------------------
__global__ void deg_k(const int* __restrict__ src, const int* __restrict__ dst) {
    int e = blockIdx.x * blockDim.x + threadIdx.x;
    if (e >= E2C) return;
    atomicAdd(&g_deg[src[e]], 1.f);
    atomicAdd(&g_deg[dst[e]], 1.f);
}

// ------------------- edge MLP (only E2 unique edges; reverse is identical) ----
__global__ __launch_bounds__(256) void edge_mlp_k(const int* __restrict__ src,
                                                  const int* __restrict__ dst,
                                                  const float* __restrict__ W1,
                                                  const float* __restrict__ B1,
                                                  const float* __restrict__ W2,
                                                  const float* __restrict__ B2) {
    __shared__ int   ss[128], dd[128];
    __shared__ float s0s[128], s1s[128];
    __shared__ float Ps[16][138], Qs[16][138];
    __shared__ float Was[16][64], Wbs[16][64];
    __shared__ float Wg0[64], Wg1[64], b1s[64], w2s[64];
    int tid = threadIdx.x;
    int e0 = blockIdx.x * 128;

    if (tid < 128) {
        int ge = e0 + tid;
        int s = src[ge], d = dst[ge];
        ss[tid] = s; dd[tid] = d;
        float degs = g_deg[s], degd = g_deg[d];
        float a = logf(degs + 1.f), b = logf(degd + 1.f);
        s0s[tid] = a + b; s1s[tid] = fabsf(a - b);
        float ds = fmaxf(degs, 1.f), dd2 = fmaxf(degd, 1.f);
        g_en[ge] = rsqrtf(ds * dd2);
    } else {
        int t = tid - 128;
        if (t < 64) { Wg0[t] = W1[512 * 64 + t]; b1s[t] = B1[t]; }
        else { int u = t - 64; Wg1[u] = W1[513 * 64 + u]; w2s[u] = W2[u]; }
    }
    __syncthreads();

    int tx = tid & 15, ty = tid >> 4;
    F2 acc[4][4];
#pragma unroll
    for (int jp = 0; jp < 4; jp++)
#pragma unroll
        for (int u = 0; u < 4; u++) acc[jp][u].f = make_float2(0.f, 0.f);

    for (int f0 = 0; f0 < HID; f0 += 16) {
#pragma unroll
        for (int i = 0; i < 2; i++) {
            int idx = tid + i * 256;
            int e = idx >> 2;
            int f4 = (idx & 3) * 4;
            float4 v = *(const float4*)(g_h + (size_t)ss[e] * HID + f0 + f4);
            float4 u = *(const float4*)(g_h + (size_t)dd[e] * HID + f0 + f4);
            Ps[f4 + 0][e] = v.x * u.x; Qs[f4 + 0][e] = fabsf(v.x - u.x);
            Ps[f4 + 1][e] = v.y * u.y; Qs[f4 + 1][e] = fabsf(v.y - u.y);
            Ps[f4 + 2][e] = v.z * u.z; Qs[f4 + 2][e] = fabsf(v.z - u.z);
            Ps[f4 + 3][e] = v.w * u.w; Qs[f4 + 3][e] = fabsf(v.w - u.w);
        }
        {
            int f = tid >> 4;
            int c4 = (tid & 15) * 4;
            *(float4*)&Was[f][c4] = *(const float4*)(W1 + (size_t)(f0 + f) * 64 + c4);
            *(float4*)&Wbs[f][c4] = *(const float4*)(W1 + (size_t)(256 + f0 + f) * 64 + c4);
        }
        __syncthreads();
#pragma unroll
        for (int f = 0; f < 16; f++) {
            F2 p2[4], q2[4];
#pragma unroll
            for (int jp = 0; jp < 4; jp++) {
                p2[jp].f = *(const float2*)&Ps[f][ty * 8 + jp * 2];
                q2[jp].f = *(const float2*)&Qs[f][ty * 8 + jp * 2];
            }
            float4 wa = *(const float4*)&Was[f][tx * 4];
            float4 wb = *(const float4*)&Wbs[f][tx * 4];
            F2 wpa[4] = {bcast2(wa.x), bcast2(wa.y), bcast2(wa.z), bcast2(wa.w)};
            F2 wpb[4] = {bcast2(wb.x), bcast2(wb.y), bcast2(wb.z), bcast2(wb.w)};
#pragma unroll
            for (int jp = 0; jp < 4; jp++)
#pragma unroll
                for (int u = 0; u < 4; u++) {
                    ffma2(acc[jp][u], p2[jp], wpa[u]);
                    ffma2(acc[jp][u], q2[jp], wpb[u]);
                }
        }
        __syncthreads();
    }
    float B2v = B2[0];
#pragma unroll
    for (int j = 0; j < 8; j++) {
        int e = ty * 8 + j;
        int jp = j >> 1;
        int hi = j & 1;
        float s0 = s0s[e], s1 = s1s[e];
        float sum = 0.f;
#pragma unroll
        for (int u4 = 0; u4 < 4; u4++) {
            int u = tx * 4 + u4;
            float a = hi ? acc[jp][u4].f.y : acc[jp][u4].f.x;
            float v = a + s0 * Wg0[u] + s1 * Wg1[u] + b1s[u];
            v = fmaxf(v, 0.f);
            sum += v * w2s[u];
        }
#pragma unroll
        for (int off = 8; off; off >>= 1)
            sum += __shfl_down_sync(0xffffffffu, sum, off, 16);
        if (tx == 0) {
            float wr = sum + B2v;
            g_w[e0 + e] = W_MAXC / (1.f + expf(-wr));
        }
    }
}

// ------------------- build per-pair kernel table K = exp(w * R) ---------------
__global__ __launch_bounds__(256) void buildK_k() {
    __shared__ float Rs[64];
    if (threadIdx.x < 64) Rs[threadIdx.x] = g_Rs[threadIdx.x];
    __syncthreads();
    int e = blockIdx.x * blockDim.x + threadIdx.x;
    if (e >= E2C) return;
    float w = g_w[e];
    float4* o = (float4*)(g_K + (size_t)e * 64);
#pragma unroll
    for (int t = 0; t < 16; t++) {
        float4 v;
        v.x = __expf(w * Rs[t * 4 + 0]);
        v.y = __expf(w * Rs[t * 4 + 1]);
        v.z = __expf(w * Rs[t * 4 + 2]);
        v.w = __expf(w * Rs[t * 4 + 3]);
        o[t] = v;
    }
}

// ------------------- init m = softmax(log_phi[src]) over all E edges ----------
__global__ void init_m_k(const int* __restrict__ srcAll) {
    int e = blockIdx.x * blockDim.x + threadIdx.x;
    if (e >= EEC) return;
    int s = srcAll[e];
    float4 A = *(const float4*)(g_logphi + s * 8);
    float4 Bv = *(const float4*)(g_logphi + s * 8 + 4);
    float lp[8] = {A.x, A.y, A.z, A.w, Bv.x, Bv.y, Bv.z, Bv.w};
    float mx = -1e30f;
#pragma unroll
    for (int c = 0; c < 8; c++) mx = fmaxf(mx, lp[c]);
    float ex[8], sm = 0.f;
#pragma unroll
    for (int c = 0; c < 8; c++) { ex[c] = expf(lp[c] - mx); sm += ex[c]; }
    float inv = 1.f / sm;
    *(float4*)(g_m + (size_t)e * 8)     = make_float4(ex[0]*inv, ex[1]*inv, ex[2]*inv, ex[3]*inv);
    *(float4*)(g_m + (size_t)e * 8 + 4) = make_float4(ex[4]*inv, ex[5]*inv, ex[6]*inv, ex[7]*inv);
}

// ------------------- helpers for BP ------------------------------------------
__device__ __forceinline__ void load8(const float* p, float* r) {
    float4 v0 = *(const float4*)p;
    float4 v1 = *(const float4*)(p + 4);
    r[0]=v0.x; r[1]=v0.y; r[2]=v0.z; r[3]=v0.w;
    r[4]=v1.x; r[5]=v1.y; r[6]=v1.z; r[7]=v1.w;
}
__device__ __forceinline__ void store8(float* p, const float* r) {
    *(float4*)p       = make_float4(r[0], r[1], r[2], r[3]);
    *(float4*)(p + 4) = make_float4(r[4], r[5], r[6], r[7]);
}
__device__ __forceinline__ void upd_m(float* mrow, const float* lp, const float* si,
                                      const float* lf_rev, float alpha) {
    float t[8], mx = -1e30f;
#pragma unroll
    for (int c = 0; c < 8; c++) { t[c] = lp[c] + alpha * (si[c] - lf_rev[c]); mx = fmaxf(mx, t[c]); }
    float ex[8], sm = 0.f;
#pragma unroll
    for (int c = 0; c < 8; c++) { ex[c] = __expf(t[c] - mx); sm += ex[c]; }
    float inv = 1.f / sm;
    float m[8], tot = 0.f;
#pragma unroll
    for (int c = 0; c < 8; c++) {
        m[c] = (1.f - ETA_C) * mrow[c] + ETA_C * (ex[c] * inv);
        m[c] = fmaxf(m[c], EPS_C);
        tot += m[c];
    }
    float it = 1.f / tot;
#pragma unroll
    for (int c = 0; c < 8; c++) mrow[c] = m[c] * it;
}

// both directions share the K row: f1 = m1 K, f2 = m2 K, then lf = log(f)*en
__device__ __forceinline__ void msg_lf2(int e, const float* m1, const float* m2,
                                        float en, float* lf1, float* lf2) {
    const F2* Kp = (const F2*)(g_K + (size_t)e * 64);
    F2 f1[4], f2[4];
#pragma unroll
    for (int u = 0; u < 4; u++) { f1[u].f = make_float2(0.f, 0.f); f2[u].f = make_float2(0.f, 0.f); }
#pragma unroll
    for (int c = 0; c < 8; c++) {
        F2 mc1 = bcast2(m1[c]);
        F2 mc2 = bcast2(m2[c]);
#pragma unroll
        for (int u = 0; u < 4; u++) {
            F2 k = Kp[c * 4 + u];
            ffma2(f1[u], mc1, k);
            ffma2(f2[u], mc2, k);
        }
    }
#pragma unroll
    for (int u = 0; u < 4; u++) {
        lf1[u*2]   = __logf(fmaxf(f1[u].f.x, EPS_C)) * en;
        lf1[u*2+1] = __logf(fmaxf(f1[u].f.y, EPS_C)) * en;
        lf2[u*2]   = __logf(fmaxf(f2[u].f.x, EPS_C)) * en;
        lf2[u*2+1] = __logf(fmaxf(f2[u].f.y, EPS_C)) * en;
    }
}

// ------------------- first half-iteration: lf & sum from current m ------------
__global__ __launch_bounds__(256) void iterA_k(const int* __restrict__ src,
                                               const int* __restrict__ dst,
                                               float* __restrict__ sum_w) {
    int e = blockIdx.x * blockDim.x + threadIdx.x;
    if (e >= E2C) return;
    float en = g_en[e];
    int s = src[e], d = dst[e];
    float m1[8], m2[8], lf1[8], lf2[8];
    load8(g_m + (size_t)e * 8, m1);
    load8(g_m + (size_t)(e + E2C) * 8, m2);
    msg_lf2(e, m1, m2, en, lf1, lf2);
    store8(g_lf + (size_t)e * 8, lf1);
    store8(g_lf + (size_t)(e + E2C) * 8, lf2);
    red4(sum_w + d * 8,     lf1[0], lf1[1], lf1[2], lf1[3]);
    red4(sum_w + d * 8 + 4, lf1[4], lf1[5], lf1[6], lf1[7]);
    red4(sum_w + s * 8,     lf2[0], lf2[1], lf2[2], lf2[3]);
    red4(sum_w + s * 8 + 4, lf2[4], lf2[5], lf2[6], lf2[7]);
}

// ------------------- fused BP iteration (update m, then new lf & sum) ---------
__global__ __launch_bounds__(256) void fused_k(const int* __restrict__ src,
                                               const int* __restrict__ dst,
                                               const float* __restrict__ sum_r,
                                               float* __restrict__ sum_w) {
    int e = blockIdx.x * blockDim.x + threadIdx.x;
    if (e >= E2C) return;
    float alpha = g_alpha;
    int s = src[e], d = dst[e];
    float lf1[8], lf2[8], m1[8], m2[8];
    load8(g_lf + (size_t)e * 8, lf1);
    load8(g_lf + (size_t)(e + E2C) * 8, lf2);
    load8(g_m + (size_t)e * 8, m1);
    load8(g_m + (size_t)(e + E2C) * 8, m2);
    {
        float lps[8], sis[8];
        load8(g_logphi + s * 8, lps);
        load8(sum_r + s * 8, sis);
        upd_m(m1, lps, sis, lf2, alpha);   // dir s->d: excl = sum[s] - lf(rev)
    }
    {
        float lpd[8], sid[8];
        load8(g_logphi + d * 8, lpd);
        load8(sum_r + d * 8, sid);
        upd_m(m2, lpd, sid, lf1, alpha);   // dir d->s: excl = sum[d] - lf1
    }
    store8(g_m + (size_t)e * 8, m1);
    store8(g_m + (size_t)(e + E2C) * 8, m2);
    float en = g_en[e];
    float nlf1[8], nlf2[8];
    msg_lf2(e, m1, m2, en, nlf1, nlf2);
    store8(g_lf + (size_t)e * 8, nlf1);
    store8(g_lf + (size_t)(e + E2C) * 8, nlf2);
    red4(sum_w + d * 8,     nlf1[0], nlf1[1], nlf1[2], nlf1[3]);
    red4(sum_w + d * 8 + 4, nlf1[4], nlf1[5], nlf1[6], nlf1[7]);
    red4(sum_w + s * 8,     nlf2[0], nlf2[1], nlf2[2], nlf2[3]);
    red4(sum_w + s * 8 + 4, nlf2[4], nlf2[5], nlf2[6], nlf2[7]);
}

// ------------------- final beliefs -------------------------------------------
__global__ void beliefs_k(const float* __restrict__ sum_r, float* __restrict__ out) {
    int n = blockIdx.x * blockDim.x + threadIdx.x;
    if (n >= NN) return;
    float alpha = g_alpha;
    float lp[8], si[8];
    load8(g_logphi + n * 8, lp);
    load8(sum_r + n * 8, si);
    float t[8], mx = -1e30f;
#pragma unroll
    for (int c = 0; c < 8; c++) { t[c] = lp[c] + alpha * si[c]; mx = fmaxf(mx, t[c]); }
    float ex[8], sm = 0.f;
#pragma unroll
    for (int c = 0; c < 8; c++) { ex[c] = expf(t[c] - mx); sm += ex[c]; }
    float inv = 1.f / sm;
    float o[8];
#pragma unroll
    for (int c = 0; c < 8; c++) o[c] = ex[c] * inv;
    store8(out + (size_t)n * 8, o);
}

// ------------------- launcher -------------------------------------------------
extern "C" void kernel_launch(void* const* d_in, const int* in_sizes, int n_in,
                              void* d_out, int out_size) {
    const float* x      = (const float*)d_in[0];
    const int*   ei     = (const int*)  d_in[1];   // [2, E] : row0 src, row1 dst
    const float* enc_w1 = (const float*)d_in[3];
    const float* enc_b1 = (const float*)d_in[4];
    const float* enc_w2 = (const float*)d_in[5];
    const float* enc_b2 = (const float*)d_in[6];
    const float* edge_w1= (const float*)d_in[7];
    const float* edge_b1= (const float*)d_in[8];
    const float* edge_w2= (const float*)d_in[9];
    const float* edge_b2= (const float*)d_in[10];
    const float* R_raw  = (const float*)d_in[11];
    const float* rsl    = (const float*)d_in[12];
    const float* msg    = (const float*)d_in[13];
    float* out = (float*)d_out;

    const int* src = ei;         // first E2 entries of row0 are unique-edge srcs
    const int* dst = ei + EEC;   // row1

    float* sumA; cudaGetSymbolAddress((void**)&sumA, g_sumA);
    float* sumB; cudaGetSymbolAddress((void**)&sumB, g_sumB);

    prep0_k<<<(NN + 255) / 256, 256>>>(R_raw, rsl, msg);
    enc_gemm_k<<<dim3((NN + 127) / 128, HID / 64), 256>>>(x, enc_w1, enc_b1);
    deg_k<<<(E2C + 255) / 256, 256>>>(src, dst);
    edge_mlp_k<<<E2C / 128, 256>>>(src, dst, edge_w1, edge_b1, edge_w2, edge_b2);
    buildK_k<<<(E2C + 255) / 256, 256>>>();
    logits_k<<<(NN * 32 + 255) / 256, 256>>>(enc_w2, enc_b2);
    init_m_k<<<(EEC + 255) / 256, 256>>>(src);  // row0 spans all E directed edges

    const int NC4 = NN * CC / 4;
    zero4_k<<<(NC4 + 255) / 256, 256>>>((float4*)sumA, NC4);
    iterA_k<<<(E2C + 255) / 256, 256>>>(src, dst, sumA);

    float* cur = sumA;
    float* nxt = sumB;
    for (int t = 0; t < T_ITERS; t++) {
        zero4_k<<<(NC4 + 255) / 256, 256>>>((float4*)nxt, NC4);
        fused_k<<<(E2C + 255) / 256, 256>>>(src, dst, cur, nxt);
        float* tmp = cur; cur = nxt; nxt = tmp;
    }
    beliefs_k<<<(NN + 255) / 256, 256>>>(cur, out);
}

// round 4
// speedup vs baseline: 1.0308x; 1.0308x over previous
#include <cuda_runtime.h>
#include <math.h>

#define NN      50000
#define INDIM   512
#define HID     256
#define CC      8
#define E2C     400000
#define EEC     800000
#define T_ITERS 10
#define ETA_C   0.2f
#define W_MAXC  0.8f
#define ALPHA_MAXC 1.5f
#define EPS_C   1e-12f

// ------------------- scratch (device globals; no allocation allowed) ---------
__device__ __align__(16) float g_h[NN * HID];        // 51.2 MB
__device__ __align__(16) float g_logphi[NN * CC];
__device__ __align__(16) float g_deg[NN];
__device__ __align__(16) float g_w[E2C];
__device__ __align__(16) float g_en[E2C];
__device__ __align__(16) float g_m[EEC * CC];        // 25.6 MB
__device__ __align__(16) float g_lf[EEC * CC];       // 25.6 MB
__device__ __align__(16) float g_sumA[NN * CC];
__device__ __align__(16) float g_sumB[NN * CC];
__device__ __align__(16) float g_Rs[64];
__device__ float g_alpha;

// ------------------- packed f32x2 FMA ----------------------------------------
union F2 { float2 f; unsigned long long u; };

__device__ __forceinline__ void ffma2(F2& d, const F2& a, const F2& b) {
    asm("fma.rn.f32x2 %0, %1, %2, %0;" : "+l"(d.u) : "l"(a.u), "l"(b.u));
}
__device__ __forceinline__ F2 bcast2(float v) {
    F2 r; r.f = make_float2(v, v); return r;
}

// ------------------- vector reduction (atomic add, no return) -----------------
__device__ __forceinline__ void red4(float* p, float a, float b, float c, float d) {
    asm volatile("red.global.add.v4.f32 [%0], {%1, %2, %3, %4};"
                 :: "l"(p), "f"(a), "f"(b), "f"(c), "f"(d) : "memory");
}

// ------------------- generic zero --------------------------------------------
__global__ void zero4_k(float4* __restrict__ p, int n4) {
    int i = blockIdx.x * blockDim.x + threadIdx.x;
    if (i < n4) p[i] = make_float4(0.f, 0.f, 0.f, 0.f);
}

// ------------------- prep: zero deg + symmetrized R + alpha -------------------
__global__ void prep0_k(const float* __restrict__ R_raw,
                        const float* __restrict__ rsl,
                        const float* __restrict__ msg) {
    int i = blockIdx.x * blockDim.x + threadIdx.x;
    if (i < NN) g_deg[i] = 0.f;
    if (blockIdx.x == 0) {
        int t = threadIdx.x;
        if (t == 0) g_alpha = ALPHA_MAXC / (1.f + expf(-msg[0]));
        if (t < 64) {
            int c = t >> 3, d = t & 7;
            float r = 0.5f * (R_raw[c * 8 + d] + R_raw[d * 8 + c]);
            float xr = rsl[0];
            float sp = (xr > 20.f) ? xr : log1pf(expf(xr));
            g_Rs[t] = (sp + 1e-6f) * tanhf(r);
        }
    }
}

// ------------------- encoder GEMM: h = relu(x @ W1 + b1) ---------------------
// block: 128 rows x 128 cols, 256 threads, 8x8 per-thread tile (FFMA2)
__global__ __launch_bounds__(256) void enc_gemm_k(const float* __restrict__ X,
                                                  const float* __restrict__ W,
                                                  const float* __restrict__ B) {
    __shared__ float Xs[16][132];
    __shared__ float Ws[16][128];
    int tid = threadIdx.x;
    int tx = tid & 15, ty = tid >> 4;
    int row0 = blockIdx.x * 128;
    int col0 = blockIdx.y * 128;
    F2 acc[4][8];
#pragma unroll
    for (int jp = 0; jp < 4; jp++)
#pragma unroll
        for (int u = 0; u < 8; u++) acc[jp][u].f = make_float2(0.f, 0.f);

    for (int k0 = 0; k0 < INDIM; k0 += 16) {
#pragma unroll
        for (int i = 0; i < 2; i++) {
            int m = (tid >> 2) + i * 64;
            int k4 = (tid & 3) * 4;
            int gr = row0 + m;
            float4 v = make_float4(0.f, 0.f, 0.f, 0.f);
            if (gr < NN) v = *(const float4*)(X + (size_t)gr * INDIM + k0 + k4);
            Xs[k4 + 0][m] = v.x; Xs[k4 + 1][m] = v.y;
            Xs[k4 + 2][m] = v.z; Xs[k4 + 3][m] = v.w;
        }
#pragma unroll
        for (int i = 0; i < 2; i++) {
            int idx = tid + i * 256;
            int k = idx >> 5;
            int c4 = (idx & 31) * 4;
            *(float4*)&Ws[k][c4] = *(const float4*)(W + (size_t)(k0 + k) * HID + col0 + c4);
        }
        __syncthreads();
#pragma unroll
        for (int kk = 0; kk < 16; kk++) {
            F2 a2[4];
#pragma unroll
            for (int jp = 0; jp < 4; jp++)
                a2[jp].f = *(const float2*)&Xs[kk][ty * 8 + jp * 2];
            float4 wA = *(const float4*)&Ws[kk][tx * 8];
            float4 wB = *(const float4*)&Ws[kk][tx * 8 + 4];
            F2 wp[8] = {bcast2(wA.x), bcast2(wA.y), bcast2(wA.z), bcast2(wA.w),
                        bcast2(wB.x), bcast2(wB.y), bcast2(wB.z), bcast2(wB.w)};
#pragma unroll
            for (int jp = 0; jp < 4; jp++)
#pragma unroll
                for (int u = 0; u < 8; u++)
                    ffma2(acc[jp][u], a2[jp], wp[u]);
        }
        __syncthreads();
    }
    float4 bA = *(const float4*)(B + col0 + tx * 8);
    float4 bB = *(const float4*)(B + col0 + tx * 8 + 4);
#pragma unroll
    for (int jp = 0; jp < 4; jp++) {
#pragma unroll
        for (int h = 0; h < 2; h++) {
            int gr = row0 + ty * 8 + jp * 2 + h;
            if (gr < NN) {
                float4 o0, o1;
                o0.x = fmaxf((h ? acc[jp][0].f.y : acc[jp][0].f.x) + bA.x, 0.f);
                o0.y = fmaxf((h ? acc[jp][1].f.y : acc[jp][1].f.x) + bA.y, 0.f);
                o0.z = fmaxf((h ? acc[jp][2].f.y : acc[jp][2].f.x) + bA.z, 0.f);
                o0.w = fmaxf((h ? acc[jp][3].f.y : acc[jp][3].f.x) + bA.w, 0.f);
                o1.x = fmaxf((h ? acc[jp][4].f.y : acc[jp][4].f.x) + bB.x, 0.f);
                o1.y = fmaxf((h ? acc[jp][5].f.y : acc[jp][5].f.x) + bB.y, 0.f);
                o1.z = fmaxf((h ? acc[jp][6].f.y : acc[jp][6].f.x) + bB.z, 0.f);
                o1.w = fmaxf((h ? acc[jp][7].f.y : acc[jp][7].f.x) + bB.w, 0.f);
                *(float4*)(g_h + (size_t)gr * HID + col0 + tx * 8)     = o0;
                *(float4*)(g_h + (size_t)gr * HID + col0 + tx * 8 + 4) = o1;
            }
        }
    }
}

// ------------------- logits + log_softmax: one warp per node ------------------
__global__ void logits_k(const float* __restrict__ W2, const float* __restrict__ B2) {
    int gt = blockIdx.x * blockDim.x + threadIdx.x;
    int node = gt >> 5, lane = gt & 31;
    if (node >= NN) return;
    const float* hrow = g_h + (size_t)node * HID;
    float acc[8];
#pragma unroll
    for (int c = 0; c < 8; c++) acc[c] = 0.f;
    for (int j = lane; j < HID; j += 32) {
        float hv = hrow[j];
        float4 wA = *(const float4*)(W2 + j * 8);
        float4 wB = *(const float4*)(W2 + j * 8 + 4);
        acc[0] += hv * wA.x; acc[1] += hv * wA.y;
        acc[2] += hv * wA.z; acc[3] += hv * wA.w;
        acc[4] += hv * wB.x; acc[5] += hv * wB.y;
        acc[6] += hv * wB.z; acc[7] += hv * wB.w;
    }
#pragma unroll
    for (int c = 0; c < 8; c++)
#pragma unroll
        for (int off = 16; off; off >>= 1)
            acc[c] += __shfl_xor_sync(0xffffffffu, acc[c], off);
    if (lane == 0) {
        float lg[8], mx = -1e30f;
#pragma unroll
        for (int c = 0; c < 8; c++) { lg[c] = acc[c] + B2[c]; mx = fmaxf(mx, lg[c]); }
        float s = 0.f;
#pragma unroll
        for (int c = 0; c < 8; c++) s += expf(lg[c] - mx);
        float lse = mx + logf(s);
        *(float4*)(g_logphi + node * 8)     = make_float4(lg[0]-lse, lg[1]-lse, lg[2]-lse, lg[3]-lse);
        *(float4*)(g_logphi + node * 8 + 4) = make_float4(lg[4]-lse, lg[5]-lse, lg[6]-lse, lg[7]-lse);
    }
}

// ------------------- degrees -------------------------------------------------
__global__ void deg_k(const int* __restrict__ src, const int* __restrict__ dst) {
    int e = blockIdx.x * blockDim.x + threadIdx.x;
    if (e >= E2C) return;
    atomicAdd(&g_deg[src[e]], 1.f);
    atomicAdd(&g_deg[dst[e]], 1.f);
}

// ------------------- edge MLP (only E2 unique edges; reverse is identical) ----
// block: 256 edges x 64 hidden; 256 threads; 8 edges x 8 cols per thread (FFMA2)
__global__ __launch_bounds__(256) void edge_mlp_k(const int* __restrict__ src,
                                                  const int* __restrict__ dst,
                                                  const float* __restrict__ W1,
                                                  const float* __restrict__ B1,
                                                  const float* __restrict__ W2,
                                                  const float* __restrict__ B2) {
    __shared__ int   ss[256], dd[256];
    __shared__ float s0s[256], s1s[256];
    __shared__ float Ps[16][258], Qs[16][258];
    __shared__ float Was[16][64], Wbs[16][64];
    __shared__ float Wg0[64], Wg1[64], b1s[64], w2s[64];
    int tid = threadIdx.x;
    int e0 = blockIdx.x * 256;

    {
        int ge = e0 + tid;
        int cge = ge < E2C ? ge : E2C - 1;
        int s = src[cge], d = dst[cge];
        ss[tid] = s; dd[tid] = d;
        float degs = g_deg[s], degd = g_deg[d];
        float a = logf(degs + 1.f), b = logf(degd + 1.f);
        s0s[tid] = a + b; s1s[tid] = fabsf(a - b);
        if (ge < E2C) {
            float ds = fmaxf(degs, 1.f), dd2 = fmaxf(degd, 1.f);
            g_en[ge] = rsqrtf(ds * dd2);
        }
        if (tid < 64)        { Wg0[tid] = W1[512 * 64 + tid]; b1s[tid] = B1[tid]; }
        else if (tid < 128)  { int u = tid - 64; Wg1[u] = W1[513 * 64 + u]; w2s[u] = W2[u]; }
    }
    __syncthreads();

    int tx = tid & 7, ty = tid >> 3;   // tx: 8 col-groups of 8; ty: 32 edge-groups of 8
    F2 acc[4][8];
#pragma unroll
    for (int jp = 0; jp < 4; jp++)
#pragma unroll
        for (int u = 0; u < 8; u++) acc[jp][u].f = make_float2(0.f, 0.f);

    for (int f0 = 0; f0 < HID; f0 += 16) {
#pragma unroll
        for (int i = 0; i < 4; i++) {
            int idx = tid + i * 256;
            int e = idx >> 2;
            int f4 = (idx & 3) * 4;
            float4 v = *(const float4*)(g_h + (size_t)ss[e] * HID + f0 + f4);
            float4 u = *(const float4*)(g_h + (size_t)dd[e] * HID + f0 + f4);
            Ps[f4 + 0][e] = v.x * u.x; Qs[f4 + 0][e] = fabsf(v.x - u.x);
            Ps[f4 + 1][e] = v.y * u.y; Qs[f4 + 1][e] = fabsf(v.y - u.y);
            Ps[f4 + 2][e] = v.z * u.z; Qs[f4 + 2][e] = fabsf(v.z - u.z);
            Ps[f4 + 3][e] = v.w * u.w; Qs[f4 + 3][e] = fabsf(v.w - u.w);
        }
        {
            int f = tid >> 4;
            int c4 = (tid & 15) * 4;
            *(float4*)&Was[f][c4] = *(const float4*)(W1 + (size_t)(f0 + f) * 64 + c4);
            *(float4*)&Wbs[f][c4] = *(const float4*)(W1 + (size_t)(256 + f0 + f) * 64 + c4);
        }
        __syncthreads();
#pragma unroll
        for (int f = 0; f < 16; f++) {
            F2 p2[4], q2[4];
#pragma unroll
            for (int jp = 0; jp < 4; jp++) {
                p2[jp].f = *(const float2*)&Ps[f][ty * 8 + jp * 2];
                q2[jp].f = *(const float2*)&Qs[f][ty * 8 + jp * 2];
            }
            float4 waA = *(const float4*)&Was[f][tx * 8];
            float4 waB = *(const float4*)&Was[f][tx * 8 + 4];
            float4 wbA = *(const float4*)&Wbs[f][tx * 8];
            float4 wbB = *(const float4*)&Wbs[f][tx * 8 + 4];
            F2 wpa[8] = {bcast2(waA.x), bcast2(waA.y), bcast2(waA.z), bcast2(waA.w),
                         bcast2(waB.x), bcast2(waB.y), bcast2(waB.z), bcast2(waB.w)};
            F2 wpb[8] = {bcast2(wbA.x), bcast2(wbA.y), bcast2(wbA.z), bcast2(wbA.w),
                         bcast2(wbB.x), bcast2(wbB.y), bcast2(wbB.z), bcast2(wbB.w)};
#pragma unroll
            for (int jp = 0; jp < 4; jp++)
#pragma unroll
                for (int u = 0; u < 8; u++) {
                    ffma2(acc[jp][u], p2[jp], wpa[u]);
                    ffma2(acc[jp][u], q2[jp], wpb[u]);
                }
        }
        __syncthreads();
    }
    // epilogue: struct features + bias + relu + w2 contraction + sigmoid
    float B2v = B2[0];
#pragma unroll
    for (int j = 0; j < 8; j++) {
        int e = ty * 8 + j;
        int jp = j >> 1;
        int hi = j & 1;
        float s0 = s0s[e], s1 = s1s[e];
        float sum = 0.f;
#pragma unroll
        for (int u8 = 0; u8 < 8; u8++) {
            int u = tx * 8 + u8;
            float a = hi ? acc[jp][u8].f.y : acc[jp][u8].f.x;
            float v = a + s0 * Wg0[u] + s1 * Wg1[u] + b1s[u];
            v = fmaxf(v, 0.f);
            sum += v * w2s[u];
        }
#pragma unroll
        for (int off = 4; off; off >>= 1)
            sum += __shfl_down_sync(0xffffffffu, sum, off, 8);
        if (tx == 0 && e0 + e < E2C) {
            float wr = sum + B2v;
            g_w[e0 + e] = W_MAXC / (1.f + expf(-wr));
        }
    }
}

// ------------------- init m = softmax(log_phi[src]) over all E edges ----------
__global__ void init_m_k(const int* __restrict__ srcAll) {
    int e = blockIdx.x * blockDim.x + threadIdx.x;
    if (e >= EEC) return;
    int s = srcAll[e];
    float4 A = *(const float4*)(g_logphi + s * 8);
    float4 Bv = *(const float4*)(g_logphi + s * 8 + 4);
    float lp[8] = {A.x, A.y, A.z, A.w, Bv.x, Bv.y, Bv.z, Bv.w};
    float mx = -1e30f;
#pragma unroll
    for (int c = 0; c < 8; c++) mx = fmaxf(mx, lp[c]);
    float ex[8], sm = 0.f;
#pragma unroll
    for (int c = 0; c < 8; c++) { ex[c] = expf(lp[c] - mx); sm += ex[c]; }
    float inv = 1.f / sm;
    *(float4*)(g_m + (size_t)e * 8)     = make_float4(ex[0]*inv, ex[1]*inv, ex[2]*inv, ex[3]*inv);
    *(float4*)(g_m + (size_t)e * 8 + 4) = make_float4(ex[4]*inv, ex[5]*inv, ex[6]*inv, ex[7]*inv);
}

// ------------------- helpers for BP ------------------------------------------
__device__ __forceinline__ void load8(const float* p, float* r) {
    float4 v0 = *(const float4*)p;
    float4 v1 = *(const float4*)(p + 4);
    r[0]=v0.x; r[1]=v0.y; r[2]=v0.z; r[3]=v0.w;
    r[4]=v1.x; r[5]=v1.y; r[6]=v1.z; r[7]=v1.w;
}
__device__ __forceinline__ void store8(float* p, const float* r) {
    *(float4*)p       = make_float4(r[0], r[1], r[2], r[3]);
    *(float4*)(p + 4) = make_float4(r[4], r[5], r[6], r[7]);
}
__device__ __forceinline__ void upd_m(float* mrow, const float* lp, const float* si,
                                      const float* lf_rev, float alpha) {
    float t[8], mx = -1e30f;
#pragma unroll
    for (int c = 0; c < 8; c++) { t[c] = lp[c] + alpha * (si[c] - lf_rev[c]); mx = fmaxf(mx, t[c]); }
    float ex[8], sm = 0.f;
#pragma unroll
    for (int c = 0; c < 8; c++) { ex[c] = __expf(t[c] - mx); sm += ex[c]; }
    float inv = 1.f / sm;
    float m[8], tot = 0.f;
#pragma unroll
    for (int c = 0; c < 8; c++) {
        m[c] = (1.f - ETA_C) * mrow[c] + ETA_C * (ex[c] * inv);
        m[c] = fmaxf(m[c], EPS_C);
        tot += m[c];
    }
    float it = 1.f / tot;
#pragma unroll
    for (int c = 0; c < 8; c++) mrow[c] = m[c] * it;
}
// both directions share the kernel row: K recomputed on the fly from w, Rs
__device__ __forceinline__ void msg_lf2(const float* Rs, float w,
                                        const float* m1, const float* m2,
                                        float en, float* lf1, float* lf2) {
    float f1[8], f2[8];
#pragma unroll
    for (int c = 0; c < 8; c++) { f1[c] = 0.f; f2[c] = 0.f; }
#pragma unroll
    for (int c = 0; c < 8; c++) {
        float mc1 = m1[c], mc2 = m2[c];
#pragma unroll
        for (int d = 0; d < 8; d++) {
            float k = __expf(w * Rs[c * 8 + d]);
            f1[d] += mc1 * k;
            f2[d] += mc2 * k;
        }
    }
#pragma unroll
    for (int c = 0; c < 8; c++) {
        lf1[c] = __logf(fmaxf(f1[c], EPS_C)) * en;
        lf2[c] = __logf(fmaxf(f2[c], EPS_C)) * en;
    }
}

// ------------------- first half-iteration: lf & sum from current m ------------
__global__ __launch_bounds__(256) void iterA_k(const int* __restrict__ src,
                                               const int* __restrict__ dst,
                                               float* __restrict__ sum_w) {
    __shared__ float Rs[64];
    if (threadIdx.x < 64) Rs[threadIdx.x] = g_Rs[threadIdx.x];
    __syncthreads();
    int e = blockIdx.x * blockDim.x + threadIdx.x;
    if (e >= E2C) return;
    float w = g_w[e], en = g_en[e];
    int s = src[e], d = dst[e];
    float m1[8], m2[8], lf1[8], lf2[8];
    load8(g_m + (size_t)e * 8, m1);
    load8(g_m + (size_t)(e + E2C) * 8, m2);
    msg_lf2(Rs, w, m1, m2, en, lf1, lf2);
    store8(g_lf + (size_t)e * 8, lf1);
    store8(g_lf + (size_t)(e + E2C) * 8, lf2);
    red4(sum_w + d * 8,     lf1[0], lf1[1], lf1[2], lf1[3]);
    red4(sum_w + d * 8 + 4, lf1[4], lf1[5], lf1[6], lf1[7]);
    red4(sum_w + s * 8,     lf2[0], lf2[1], lf2[2], lf2[3]);
    red4(sum_w + s * 8 + 4, lf2[4], lf2[5], lf2[6], lf2[7]);
}

// ------------------- fused BP iteration (update m, then new lf & sum) ---------
__global__ __launch_bounds__(256) void fused_k(const int* __restrict__ src,
                                               const int* __restrict__ dst,
                                               const float* __restrict__ sum_r,
                                               float* __restrict__ sum_w) {
    __shared__ float Rs[64];
    if (threadIdx.x < 64) Rs[threadIdx.x] = g_Rs[threadIdx.x];
    __syncthreads();
    int e = blockIdx.x * blockDim.x + threadIdx.x;
    if (e >= E2C) return;
    float alpha = g_alpha;
    int s = src[e], d = dst[e];
    float lf1[8], lf2[8], m1[8], m2[8];
    load8(g_lf + (size_t)e * 8, lf1);
    load8(g_lf + (size_t)(e + E2C) * 8, lf2);
    load8(g_m + (size_t)e * 8, m1);
    load8(g_m + (size_t)(e + E2C) * 8, m2);
    {
        float lps[8], sis[8];
        load8(g_logphi + s * 8, lps);
        load8(sum_r + s * 8, sis);
        upd_m(m1, lps, sis, lf2, alpha);   // dir s->d: excl = sum[s] - lf(rev)
    }
    {
        float lpd[8], sid[8];
        load8(g_logphi + d * 8, lpd);
        load8(sum_r + d * 8, sid);
        upd_m(m2, lpd, sid, lf1, alpha);   // dir d->s: excl = sum[d] - lf1
    }
    store8(g_m + (size_t)e * 8, m1);
    store8(g_m + (size_t)(e + E2C) * 8, m2);
    float w = g_w[e], en = g_en[e];
    float nlf1[8], nlf2[8];
    msg_lf2(Rs, w, m1, m2, en, nlf1, nlf2);
    store8(g_lf + (size_t)e * 8, nlf1);
    store8(g_lf + (size_t)(e + E2C) * 8, nlf2);
    red4(sum_w + d * 8,     nlf1[0], nlf1[1], nlf1[2], nlf1[3]);
    red4(sum_w + d * 8 + 4, nlf1[4], nlf1[5], nlf1[6], nlf1[7]);
    red4(sum_w + s * 8,     nlf2[0], nlf2[1], nlf2[2], nlf2[3]);
    red4(sum_w + s * 8 + 4, nlf2[4], nlf2[5], nlf2[6], nlf2[7]);
}

// ------------------- final beliefs -------------------------------------------
__global__ void beliefs_k(const float* __restrict__ sum_r, float* __restrict__ out) {
    int n = blockIdx.x * blockDim.x + threadIdx.x;
    if (n >= NN) return;
    float alpha = g_alpha;
    float lp[8], si[8];
    load8(g_logphi + n * 8, lp);
    load8(sum_r + n * 8, si);
    float t[8], mx = -1e30f;
#pragma unroll
    for (int c = 0; c < 8; c++) { t[c] = lp[c] + alpha * si[c]; mx = fmaxf(mx, t[c]); }
    float ex[8], sm = 0.f;
#pragma unroll
    for (int c = 0; c < 8; c++) { ex[c] = expf(t[c] - mx); sm += ex[c]; }
    float inv = 1.f / sm;
    float o[8];
#pragma unroll
    for (int c = 0; c < 8; c++) o[c] = ex[c] * inv;
    store8(out + (size_t)n * 8, o);
}

// ------------------- launcher -------------------------------------------------
extern "C" void kernel_launch(void* const* d_in, const int* in_sizes, int n_in,
                              void* d_out, int out_size) {
    const float* x      = (const float*)d_in[0];
    const int*   ei     = (const int*)  d_in[1];   // [2, E] : row0 src, row1 dst
    const float* enc_w1 = (const float*)d_in[3];
    const float* enc_b1 = (const float*)d_in[4];
    const float* enc_w2 = (const float*)d_in[5];
    const float* enc_b2 = (const float*)d_in[6];
    const float* edge_w1= (const float*)d_in[7];
    const float* edge_b1= (const float*)d_in[8];
    const float* edge_w2= (const float*)d_in[9];
    const float* edge_b2= (const float*)d_in[10];
    const float* R_raw  = (const float*)d_in[11];
    const float* rsl    = (const float*)d_in[12];
    const float* msg    = (const float*)d_in[13];
    float* out = (float*)d_out;

    const int* src = ei;         // first E2 entries of row0 are unique-edge srcs
    const int* dst = ei + EEC;   // row1

    float* sumA; cudaGetSymbolAddress((void**)&sumA, g_sumA);
    float* sumB; cudaGetSymbolAddress((void**)&sumB, g_sumB);

    prep0_k<<<(NN + 255) / 256, 256>>>(R_raw, rsl, msg);
    enc_gemm_k<<<dim3((NN + 127) / 128, HID / 128), 256>>>(x, enc_w1, enc_b1);
    deg_k<<<(E2C + 255) / 256, 256>>>(src, dst);
    edge_mlp_k<<<(E2C + 255) / 256, 256>>>(src, dst, edge_w1, edge_b1, edge_w2, edge_b2);
    logits_k<<<(NN * 32 + 255) / 256, 256>>>(enc_w2, enc_b2);
    init_m_k<<<(EEC + 255) / 256, 256>>>(src);  // row0 spans all E directed edges

    const int NC4 = NN * CC / 4;
    zero4_k<<<(NC4 + 255) / 256, 256>>>((float4*)sumA, NC4);
    iterA_k<<<(E2C + 255) / 256, 256>>>(src, dst, sumA);

    float* cur = sumA;
    float* nxt = sumB;
    for (int t = 0; t < T_ITERS; t++) {
        zero4_k<<<(NC4 + 255) / 256, 256>>>((float4*)nxt, NC4);
        fused_k<<<(E2C + 255) / 256, 256>>>(src, dst, cur, nxt);
        float* tmp = cur; cur = nxt; nxt = tmp;
    }
    beliefs_k<<<(NN + 255) / 256, 256>>>(cur, out);
}

// round 5
// speedup vs baseline: 1.4203x; 1.3779x over previous
#include <cuda_runtime.h>
#include <math.h>

#define NN      50000
#define INDIM   512
#define HID     256
#define CC      8
#define E2C     400000
#define EEC     800000
#define T_ITERS 10
#define ETA_C   0.2f
#define W_MAXC  0.8f
#define ALPHA_MAXC 1.5f
#define EPS_C   1e-12f

// ------------------- scratch (device globals; no allocation allowed) ---------
__device__ __align__(16) float g_h[NN * HID];        // 51.2 MB
__device__ __align__(16) float g_logphi[NN * CC];
__device__ __align__(16) float g_deg[NN];
__device__ __align__(16) float g_w[E2C];
__device__ __align__(16) float g_en[E2C];
__device__ __align__(16) float g_m[EEC * CC];        // 25.6 MB
__device__ __align__(16) float g_lf[EEC * CC];       // 25.6 MB
__device__ __align__(16) float g_sumA[NN * CC];
__device__ __align__(16) float g_sumB[NN * CC];
__device__ __align__(16) float g_Rs[64];
__device__ float g_alpha;

// ------------------- packed f32x2 FMA ----------------------------------------
union F2 { float2 f; unsigned long long u; };

__device__ __forceinline__ void ffma2(F2& d, const F2& a, const F2& b) {
    asm("fma.rn.f32x2 %0, %1, %2, %0;" : "+l"(d.u) : "l"(a.u), "l"(b.u));
}
__device__ __forceinline__ F2 bcast2(float v) {
    F2 r; r.f = make_float2(v, v); return r;
}

// ------------------- tf32 helpers --------------------------------------------
__device__ __forceinline__ float tf32r(float x) {
    unsigned o;
    asm("cvt.rna.tf32.f32 %0, %1;" : "=r"(o) : "f"(x));
    return __uint_as_float(o);
}

// ------------------- vector reduction (atomic add, no return) -----------------
__device__ __forceinline__ void red4(float* p, float a, float b, float c, float d) {
    asm volatile("red.global.add.v4.f32 [%0], {%1, %2, %3, %4};"
                 :: "l"(p), "f"(a), "f"(b), "f"(c), "f"(d) : "memory");
}

// ------------------- generic zero --------------------------------------------
__global__ void zero4_k(float4* __restrict__ p, int n4) {
    int i = blockIdx.x * blockDim.x + threadIdx.x;
    if (i < n4) p[i] = make_float4(0.f, 0.f, 0.f, 0.f);
}

// ------------------- prep: zero deg + symmetrized R + alpha -------------------
__global__ void prep0_k(const float* __restrict__ R_raw,
                        const float* __restrict__ rsl,
                        const float* __restrict__ msg) {
    int i = blockIdx.x * blockDim.x + threadIdx.x;
    if (i < NN) g_deg[i] = 0.f;
    if (blockIdx.x == 0) {
        int t = threadIdx.x;
        if (t == 0) g_alpha = ALPHA_MAXC / (1.f + expf(-msg[0]));
        if (t < 64) {
            int c = t >> 3, d = t & 7;
            float r = 0.5f * (R_raw[c * 8 + d] + R_raw[d * 8 + c]);
            float xr = rsl[0];
            float sp = (xr > 20.f) ? xr : log1pf(expf(xr));
            g_Rs[t] = (sp + 1e-6f) * tanhf(r);
        }
    }
}

// ------------------- encoder GEMM: h = relu(x @ W1 + b1) ---------------------
// block: 128 rows x 128 cols, 256 threads, 8x8 per-thread tile (FFMA2)
__global__ __launch_bounds__(256) void enc_gemm_k(const float* __restrict__ X,
                                                  const float* __restrict__ W,
                                                  const float* __restrict__ B) {
    __shared__ float Xs[16][132];
    __shared__ float Ws[16][128];
    int tid = threadIdx.x;
    int tx = tid & 15, ty = tid >> 4;
    int row0 = blockIdx.x * 128;
    int col0 = blockIdx.y * 128;
    F2 acc[4][8];
#pragma unroll
    for (int jp = 0; jp < 4; jp++)
#pragma unroll
        for (int u = 0; u < 8; u++) acc[jp][u].f = make_float2(0.f, 0.f);

    for (int k0 = 0; k0 < INDIM; k0 += 16) {
#pragma unroll
        for (int i = 0; i < 2; i++) {
            int m = (tid >> 2) + i * 64;
            int k4 = (tid & 3) * 4;
            int gr = row0 + m;
            float4 v = make_float4(0.f, 0.f, 0.f, 0.f);
            if (gr < NN) v = *(const float4*)(X + (size_t)gr * INDIM + k0 + k4);
            Xs[k4 + 0][m] = v.x; Xs[k4 + 1][m] = v.y;
            Xs[k4 + 2][m] = v.z; Xs[k4 + 3][m] = v.w;
        }
#pragma unroll
        for (int i = 0; i < 2; i++) {
            int idx = tid + i * 256;
            int k = idx >> 5;
            int c4 = (idx & 31) * 4;
            *(float4*)&Ws[k][c4] = *(const float4*)(W + (size_t)(k0 + k) * HID + col0 + c4);
        }
        __syncthreads();
#pragma unroll
        for (int kk = 0; kk < 16; kk++) {
            F2 a2[4];
#pragma unroll
            for (int jp = 0; jp < 4; jp++)
                a2[jp].f = *(const float2*)&Xs[kk][ty * 8 + jp * 2];
            float4 wA = *(const float4*)&Ws[kk][tx * 8];
            float4 wB = *(const float4*)&Ws[kk][tx * 8 + 4];
            F2 wp[8] = {bcast2(wA.x), bcast2(wA.y), bcast2(wA.z), bcast2(wA.w),
                        bcast2(wB.x), bcast2(wB.y), bcast2(wB.z), bcast2(wB.w)};
#pragma unroll
            for (int jp = 0; jp < 4; jp++)
#pragma unroll
                for (int u = 0; u < 8; u++)
                    ffma2(acc[jp][u], a2[jp], wp[u]);
        }
        __syncthreads();
    }
    float4 bA = *(const float4*)(B + col0 + tx * 8);
    float4 bB = *(const float4*)(B + col0 + tx * 8 + 4);
#pragma unroll
    for (int jp = 0; jp < 4; jp++) {
#pragma unroll
        for (int h = 0; h < 2; h++) {
            int gr = row0 + ty * 8 + jp * 2 + h;
            if (gr < NN) {
                float4 o0, o1;
                o0.x = fmaxf((h ? acc[jp][0].f.y : acc[jp][0].f.x) + bA.x, 0.f);
                o0.y = fmaxf((h ? acc[jp][1].f.y : acc[jp][1].f.x) + bA.y, 0.f);
                o0.z = fmaxf((h ? acc[jp][2].f.y : acc[jp][2].f.x) + bA.z, 0.f);
                o0.w = fmaxf((h ? acc[jp][3].f.y : acc[jp][3].f.x) + bA.w, 0.f);
                o1.x = fmaxf((h ? acc[jp][4].f.y : acc[jp][4].f.x) + bB.x, 0.f);
                o1.y = fmaxf((h ? acc[jp][5].f.y : acc[jp][5].f.x) + bB.y, 0.f);
                o1.z = fmaxf((h ? acc[jp][6].f.y : acc[jp][6].f.x) + bB.z, 0.f);
                o1.w = fmaxf((h ? acc[jp][7].f.y : acc[jp][7].f.x) + bB.w, 0.f);
                *(float4*)(g_h + (size_t)gr * HID + col0 + tx * 8)     = o0;
                *(float4*)(g_h + (size_t)gr * HID + col0 + tx * 8 + 4) = o1;
            }
        }
    }
}

// ------------------- logits + log_softmax: one warp per node ------------------
__global__ void logits_k(const float* __restrict__ W2, const float* __restrict__ B2) {
    int gt = blockIdx.x * blockDim.x + threadIdx.x;
    int node = gt >> 5, lane = gt & 31;
    if (node >= NN) return;
    const float* hrow = g_h + (size_t)node * HID;
    float acc[8];
#pragma unroll
    for (int c = 0; c < 8; c++) acc[c] = 0.f;
    for (int j = lane; j < HID; j += 32) {
        float hv = hrow[j];
        float4 wA = *(const float4*)(W2 + j * 8);
        float4 wB = *(const float4*)(W2 + j * 8 + 4);
        acc[0] += hv * wA.x; acc[1] += hv * wA.y;
        acc[2] += hv * wA.z; acc[3] += hv * wA.w;
        acc[4] += hv * wB.x; acc[5] += hv * wB.y;
        acc[6] += hv * wB.z; acc[7] += hv * wB.w;
    }
#pragma unroll
    for (int c = 0; c < 8; c++)
#pragma unroll
        for (int off = 16; off; off >>= 1)
            acc[c] += __shfl_xor_sync(0xffffffffu, acc[c], off);
    if (lane == 0) {
        float lg[8], mx = -1e30f;
#pragma unroll
        for (int c = 0; c < 8; c++) { lg[c] = acc[c] + B2[c]; mx = fmaxf(mx, lg[c]); }
        float s = 0.f;
#pragma unroll
        for (int c = 0; c < 8; c++) s += expf(lg[c] - mx);
        float lse = mx + logf(s);
        *(float4*)(g_logphi + node * 8)     = make_float4(lg[0]-lse, lg[1]-lse, lg[2]-lse, lg[3]-lse);
        *(float4*)(g_logphi + node * 8 + 4) = make_float4(lg[4]-lse, lg[5]-lse, lg[6]-lse, lg[7]-lse);
    }
}

// ------------------- degrees -------------------------------------------------
__global__ void deg_k(const int* __restrict__ src, const int* __restrict__ dst) {
    int e = blockIdx.x * blockDim.x + threadIdx.x;
    if (e >= E2C) return;
    atomicAdd(&g_deg[src[e]], 1.f);
    atomicAdd(&g_deg[dst[e]], 1.f);
}

// ------------------- edge MLP via tf32 mma.sync -------------------------------
// block: 128 edges x 64 hidden, K=512 (P:256 | Q:256), 8 warps (4 m x 2 n)
// smem: A tiles [part][128 edges][36] (kc=32), B tiles [part][32][68]
__global__ __launch_bounds__(256) void edge_mlp_k(const int* __restrict__ src,
                                                  const int* __restrict__ dst,
                                                  const float* __restrict__ W1,
                                                  const float* __restrict__ B1,
                                                  const float* __restrict__ W2,
                                                  const float* __restrict__ B2) {
    __shared__ int   ss[128], dd[128];
    __shared__ float s0s[128], s1s[128];
    __shared__ float As[2][128][36];   // 36.9 KB  [part][edge(m)][k]
    __shared__ float Bs[2][32][68];    // 17.4 KB  [part][k][n]
    __shared__ float Wg0[64], Wg1[64], b1s[64], w2s[64];
    __shared__ float wsum[128];

    int tid  = threadIdx.x;
    int wid  = tid >> 5;
    int lane = tid & 31;
    int gid  = lane >> 2;      // group id 0..7
    int tg   = lane & 3;       // thread-in-group 0..3
    int warp_m = wid & 3;      // 4 m-warps * 32 edges
    int warp_n = wid >> 2;     // 2 n-warps * 32 cols
    int e0 = blockIdx.x * 128;

    if (tid < 128) {
        int ge = e0 + tid;
        int s = src[ge], d = dst[ge];
        ss[tid] = s; dd[tid] = d;
        float degs = g_deg[s], degd = g_deg[d];
        float a = logf(degs + 1.f), b = logf(degd + 1.f);
        s0s[tid] = a + b; s1s[tid] = fabsf(a - b);
        float ds = fmaxf(degs, 1.f), dd2 = fmaxf(degd, 1.f);
        g_en[ge] = rsqrtf(ds * dd2);
        wsum[tid] = 0.f;
    } else {
        int t = tid - 128;
        if (t < 64) { Wg0[t] = W1[512 * 64 + t]; b1s[t] = B1[t]; }
        else { int u = t - 64; Wg1[u] = W1[513 * 64 + u]; w2s[u] = W2[u]; }
    }
    __syncthreads();

    float acc[2][4][4];
#pragma unroll
    for (int mt = 0; mt < 2; mt++)
#pragma unroll
        for (int nt = 0; nt < 4; nt++)
#pragma unroll
            for (int r = 0; r < 4; r++) acc[mt][nt][r] = 0.f;

    for (int f0 = 0; f0 < HID; f0 += 32) {
        // ---- stage A: P/Q for 128 edges x 32 feats (2 threads per edge) ----
        {
            int e = tid >> 1;
            int half = tid & 1;
            const float4* hs4 = (const float4*)(g_h + (size_t)ss[e] * HID + f0 + half * 16);
            const float4* hd4 = (const float4*)(g_h + (size_t)dd[e] * HID + f0 + half * 16);
#pragma unroll
            for (int j = 0; j < 4; j++) {
                float4 a = hs4[j];
                float4 b = hd4[j];
                float4 p, q;
                p.x = tf32r(a.x * b.x); q.x = tf32r(fabsf(a.x - b.x));
                p.y = tf32r(a.y * b.y); q.y = tf32r(fabsf(a.y - b.y));
                p.z = tf32r(a.z * b.z); q.z = tf32r(fabsf(a.z - b.z));
                p.w = tf32r(a.w * b.w); q.w = tf32r(fabsf(a.w - b.w));
                *(float4*)&As[0][e][half * 16 + j * 4] = p;
                *(float4*)&As[1][e][half * 16 + j * 4] = q;
            }
        }
        // ---- stage B: W1 rows f0..f0+31 (P part) and 256+f0.. (Q part) ----
#pragma unroll
        for (int i = 0; i < 2; i++) {
            int idx = tid + i * 256;       // 0..511 float4 units
            int r = idx >> 4;              // 0..31
            int c4 = (idx & 15) * 4;
            float4 wa = *(const float4*)(W1 + (size_t)(f0 + r) * 64 + c4);
            float4 wb = *(const float4*)(W1 + (size_t)(256 + f0 + r) * 64 + c4);
            wa.x = tf32r(wa.x); wa.y = tf32r(wa.y); wa.z = tf32r(wa.z); wa.w = tf32r(wa.w);
            wb.x = tf32r(wb.x); wb.y = tf32r(wb.y); wb.z = tf32r(wb.z); wb.w = tf32r(wb.w);
            *(float4*)&Bs[0][r][c4] = wa;
            *(float4*)&Bs[1][r][c4] = wb;
        }
        __syncthreads();

        // ---- compute: 2 parts x 4 k8 steps ----
#pragma unroll
        for (int part = 0; part < 2; part++) {
#pragma unroll
            for (int k8 = 0; k8 < 4; k8++) {
                int kb = k8 * 8;
                unsigned b0[4], b1[4];
#pragma unroll
                for (int nt = 0; nt < 4; nt++) {
                    int n = warp_n * 32 + nt * 8 + gid;
                    b0[nt] = __float_as_uint(Bs[part][kb + tg][n]);
                    b1[nt] = __float_as_uint(Bs[part][kb + 4 + tg][n]);
                }
#pragma unroll
                for (int mt = 0; mt < 2; mt++) {
                    int m = warp_m * 32 + mt * 16;
                    unsigned a0 = __float_as_uint(As[part][m + gid][kb + tg]);
                    unsigned a1 = __float_as_uint(As[part][m + 8 + gid][kb + tg]);
                    unsigned a2 = __float_as_uint(As[part][m + gid][kb + 4 + tg]);
                    unsigned a3 = __float_as_uint(As[part][m + 8 + gid][kb + 4 + tg]);
#pragma unroll
                    for (int nt = 0; nt < 4; nt++) {
                        asm("mma.sync.aligned.m16n8k8.row.col.f32.tf32.tf32.f32 "
                            "{%0,%1,%2,%3}, {%4,%5,%6,%7}, {%8,%9}, {%0,%1,%2,%3};"
                            : "+f"(acc[mt][nt][0]), "+f"(acc[mt][nt][1]),
                              "+f"(acc[mt][nt][2]), "+f"(acc[mt][nt][3])
                            : "r"(a0), "r"(a1), "r"(a2), "r"(a3),
                              "r"(b0[nt]), "r"(b1[nt]));
                    }
                }
            }
        }
        __syncthreads();
    }

    // ---- epilogue: struct feats + bias + relu + w2 dot, reduce into wsum ----
#pragma unroll
    for (int mt = 0; mt < 2; mt++) {
#pragma unroll
        for (int rh = 0; rh < 2; rh++) {
            int e = warp_m * 32 + mt * 16 + rh * 8 + gid;
            float s0 = s0s[e], s1 = s1s[e];
            float partial = 0.f;
#pragma unroll
            for (int nt = 0; nt < 4; nt++) {
#pragma unroll
                for (int cc = 0; cc < 2; cc++) {
                    int u = warp_n * 32 + nt * 8 + 2 * tg + cc;
                    float v = acc[mt][nt][rh * 2 + cc];
                    v += s0 * Wg0[u] + s1 * Wg1[u] + b1s[u];
                    v = fmaxf(v, 0.f);
                    partial += v * w2s[u];
                }
            }
            atomicAdd(&wsum[e], partial);
        }
    }
    __syncthreads();
    if (tid < 128) {
        float wr = wsum[tid] + B2[0];
        g_w[e0 + tid] = W_MAXC / (1.f + expf(-wr));
    }
}

// ------------------- init m = softmax(log_phi[src]) over all E edges ----------
__global__ void init_m_k(const int* __restrict__ srcAll) {
    int e = blockIdx.x * blockDim.x + threadIdx.x;
    if (e >= EEC) return;
    int s = srcAll[e];
    float4 A = *(const float4*)(g_logphi + s * 8);
    float4 Bv = *(const float4*)(g_logphi + s * 8 + 4);
    float lp[8] = {A.x, A.y, A.z, A.w, Bv.x, Bv.y, Bv.z, Bv.w};
    float mx = -1e30f;
#pragma unroll
    for (int c = 0; c < 8; c++) mx = fmaxf(mx, lp[c]);
    float ex[8], sm = 0.f;
#pragma unroll
    for (int c = 0; c < 8; c++) { ex[c] = expf(lp[c] - mx); sm += ex[c]; }
    float inv = 1.f / sm;
    *(float4*)(g_m + (size_t)e * 8)     = make_float4(ex[0]*inv, ex[1]*inv, ex[2]*inv, ex[3]*inv);
    *(float4*)(g_m + (size_t)e * 8 + 4) = make_float4(ex[4]*inv, ex[5]*inv, ex[6]*inv, ex[7]*inv);
}

// ------------------- helpers for BP ------------------------------------------
__device__ __forceinline__ void load8(const float* p, float* r) {
    float4 v0 = *(const float4*)p;
    float4 v1 = *(const float4*)(p + 4);
    r[0]=v0.x; r[1]=v0.y; r[2]=v0.z; r[3]=v0.w;
    r[4]=v1.x; r[5]=v1.y; r[6]=v1.z; r[7]=v1.w;
}
__device__ __forceinline__ void store8(float* p, const float* r) {
    *(float4*)p       = make_float4(r[0], r[1], r[2], r[3]);
    *(float4*)(p + 4) = make_float4(r[4], r[5], r[6], r[7]);
}
__device__ __forceinline__ void upd_m(float* mrow, const float* lp, const float* si,
                                      const float* lf_rev, float alpha) {
    float t[8], mx = -1e30f;
#pragma unroll
    for (int c = 0; c < 8; c++) { t[c] = lp[c] + alpha * (si[c] - lf_rev[c]); mx = fmaxf(mx, t[c]); }
    float ex[8], sm = 0.f;
#pragma unroll
    for (int c = 0; c < 8; c++) { ex[c] = __expf(t[c] - mx); sm += ex[c]; }
    float inv = 1.f / sm;
    float m[8], tot = 0.f;
#pragma unroll
    for (int c = 0; c < 8; c++) {
        m[c] = (1.f - ETA_C) * mrow[c] + ETA_C * (ex[c] * inv);
        m[c] = fmaxf(m[c], EPS_C);
        tot += m[c];
    }
    float it = 1.f / tot;
#pragma unroll
    for (int c = 0; c < 8; c++) mrow[c] = m[c] * it;
}
// both directions share the kernel row: K recomputed on the fly from w, Rs
__device__ __forceinline__ void msg_lf2(const float* Rs, float w,
                                        const float* m1, const float* m2,
                                        float en, float* lf1, float* lf2) {
    float f1[8], f2[8];
#pragma unroll
    for (int c = 0; c < 8; c++) { f1[c] = 0.f; f2[c] = 0.f; }
#pragma unroll
    for (int c = 0; c < 8; c++) {
        float mc1 = m1[c], mc2 = m2[c];
#pragma unroll
        for (int d = 0; d < 8; d++) {
            float k = __expf(w * Rs[c * 8 + d]);
            f1[d] += mc1 * k;
            f2[d] += mc2 * k;
        }
    }
#pragma unroll
    for (int c = 0; c < 8; c++) {
        lf1[c] = __logf(fmaxf(f1[c], EPS_C)) * en;
        lf2[c] = __logf(fmaxf(f2[c], EPS_C)) * en;
    }
}

// ------------------- first half-iteration: lf & sum from current m ------------
__global__ __launch_bounds__(256) void iterA_k(const int* __restrict__ src,
                                               const int* __restrict__ dst,
                                               float* __restrict__ sum_w) {
    __shared__ float Rs[64];
    if (threadIdx.x < 64) Rs[threadIdx.x] = g_Rs[threadIdx.x];
    __syncthreads();
    int e = blockIdx.x * blockDim.x + threadIdx.x;
    if (e >= E2C) return;
    float w = g_w[e], en = g_en[e];
    int s = src[e], d = dst[e];
    float m1[8], m2[8], lf1[8], lf2[8];
    load8(g_m + (size_t)e * 8, m1);
    load8(g_m + (size_t)(e + E2C) * 8, m2);
    msg_lf2(Rs, w, m1, m2, en, lf1, lf2);
    store8(g_lf + (size_t)e * 8, lf1);
    store8(g_lf + (size_t)(e + E2C) * 8, lf2);
    red4(sum_w + d * 8,     lf1[0], lf1[1], lf1[2], lf1[3]);
    red4(sum_w + d * 8 + 4, lf1[4], lf1[5], lf1[6], lf1[7]);
    red4(sum_w + s * 8,     lf2[0], lf2[1], lf2[2], lf2[3]);
    red4(sum_w + s * 8 + 4, lf2[4], lf2[5], lf2[6], lf2[7]);
}

// ------------------- fused BP iteration (update m, then new lf & sum) ---------
__global__ __launch_bounds__(256) void fused_k(const int* __restrict__ src,
                                               const int* __restrict__ dst,
                                               const float* __restrict__ sum_r,
                                               float* __restrict__ sum_w) {
    __shared__ float Rs[64];
    if (threadIdx.x < 64) Rs[threadIdx.x] = g_Rs[threadIdx.x];
    __syncthreads();
    int e = blockIdx.x * blockDim.x + threadIdx.x;
    if (e >= E2C) return;
    float alpha = g_alpha;
    int s = src[e], d = dst[e];
    float lf1[8], lf2[8], m1[8], m2[8];
    load8(g_lf + (size_t)e * 8, lf1);
    load8(g_lf + (size_t)(e + E2C) * 8, lf2);
    load8(g_m + (size_t)e * 8, m1);
    load8(g_m + (size_t)(e + E2C) * 8, m2);
    {
        float lps[8], sis[8];
        load8(g_logphi + s * 8, lps);
        load8(sum_r + s * 8, sis);
        upd_m(m1, lps, sis, lf2, alpha);   // dir s->d: excl = sum[s] - lf(rev)
    }
    {
        float lpd[8], sid[8];
        load8(g_logphi + d * 8, lpd);
        load8(sum_r + d * 8, sid);
        upd_m(m2, lpd, sid, lf1, alpha);   // dir d->s: excl = sum[d] - lf1
    }
    store8(g_m + (size_t)e * 8, m1);
    store8(g_m + (size_t)(e + E2C) * 8, m2);
    float w = g_w[e], en = g_en[e];
    float nlf1[8], nlf2[8];
    msg_lf2(Rs, w, m1, m2, en, nlf1, nlf2);
    store8(g_lf + (size_t)e * 8, nlf1);
    store8(g_lf + (size_t)(e + E2C) * 8, nlf2);
    red4(sum_w + d * 8,     nlf1[0], nlf1[1], nlf1[2], nlf1[3]);
    red4(sum_w + d * 8 + 4, nlf1[4], nlf1[5], nlf1[6], nlf1[7]);
    red4(sum_w + s * 8,     nlf2[0], nlf2[1], nlf2[2], nlf2[3]);
    red4(sum_w + s * 8 + 4, nlf2[4], nlf2[5], nlf2[6], nlf2[7]);
}

// ------------------- final beliefs -------------------------------------------
__global__ void beliefs_k(const float* __restrict__ sum_r, float* __restrict__ out) {
    int n = blockIdx.x * blockDim.x + threadIdx.x;
    if (n >= NN) return;
    float alpha = g_alpha;
    float lp[8], si[8];
    load8(g_logphi + n * 8, lp);
    load8(sum_r + n * 8, si);
    float t[8], mx = -1e30f;
#pragma unroll
    for (int c = 0; c < 8; c++) { t[c] = lp[c] + alpha * si[c]; mx = fmaxf(mx, t[c]); }
    float ex[8], sm = 0.f;
#pragma unroll
    for (int c = 0; c < 8; c++) { ex[c] = expf(t[c] - mx); sm += ex[c]; }
    float inv = 1.f / sm;
    float o[8];
#pragma unroll
    for (int c = 0; c < 8; c++) o[c] = ex[c] * inv;
    store8(out + (size_t)n * 8, o);
}

// ------------------- launcher -------------------------------------------------
extern "C" void kernel_launch(void* const* d_in, const int* in_sizes, int n_in,
                              void* d_out, int out_size) {
    const float* x      = (const float*)d_in[0];
    const int*   ei     = (const int*)  d_in[1];   // [2, E] : row0 src, row1 dst
    const float* enc_w1 = (const float*)d_in[3];
    const float* enc_b1 = (const float*)d_in[4];
    const float* enc_w2 = (const float*)d_in[5];
    const float* enc_b2 = (const float*)d_in[6];
    const float* edge_w1= (const float*)d_in[7];
    const float* edge_b1= (const float*)d_in[8];
    const float* edge_w2= (const float*)d_in[9];
    const float* edge_b2= (const float*)d_in[10];
    const float* R_raw  = (const float*)d_in[11];
    const float* rsl    = (const float*)d_in[12];
    const float* msg    = (const float*)d_in[13];
    float* out = (float*)d_out;

    const int* src = ei;         // first E2 entries of row0 are unique-edge srcs
    const int* dst = ei + EEC;   // row1

    float* sumA; cudaGetSymbolAddress((void**)&sumA, g_sumA);
    float* sumB; cudaGetSymbolAddress((void**)&sumB, g_sumB);

    prep0_k<<<(NN + 255) / 256, 256>>>(R_raw, rsl, msg);
    enc_gemm_k<<<dim3((NN + 127) / 128, HID / 128), 256>>>(x, enc_w1, enc_b1);
    deg_k<<<(E2C + 255) / 256, 256>>>(src, dst);
    edge_mlp_k<<<E2C / 128, 256>>>(src, dst, edge_w1, edge_b1, edge_w2, edge_b2);
    logits_k<<<(NN * 32 + 255) / 256, 256>>>(enc_w2, enc_b2);
    init_m_k<<<(EEC + 255) / 256, 256>>>(src);  // row0 spans all E directed edges

    const int NC4 = NN * CC / 4;
    zero4_k<<<(NC4 + 255) / 256, 256>>>((float4*)sumA, NC4);
    iterA_k<<<(E2C + 255) / 256, 256>>>(src, dst, sumA);

    float* cur = sumA;
    float* nxt = sumB;
    for (int t = 0; t < T_ITERS; t++) {
        zero4_k<<<(NC4 + 255) / 256, 256>>>((float4*)nxt, NC4);
        fused_k<<<(E2C + 255) / 256, 256>>>(src, dst, cur, nxt);
        float* tmp = cur; cur = nxt; nxt = tmp;
    }
    beliefs_k<<<(NN + 255) / 256, 256>>>(cur, out);
}

// round 6
// speedup vs baseline: 1.5300x; 1.0772x over previous
#include <cuda_runtime.h>
#include <cuda_fp16.h>
#include <math.h>

#define NN      50000
#define INDIM   512
#define HID     256
#define CC      8
#define E2C     400000
#define EEC     800000
#define T_ITERS 10
#define ETA_C   0.2f
#define W_MAXC  0.8f
#define ALPHA_MAXC 1.5f
#define EPS_C   1e-12f

// ------------------- scratch (device globals; no allocation allowed) ---------
__device__ __align__(16) float g_h[NN * HID];        // 51.2 MB
__device__ __align__(16) float g_logphi[NN * CC];
__device__ __align__(16) float g_deg[NN];
__device__ __align__(16) float g_w[E2C];
__device__ __align__(16) float g_en[E2C];
__device__ __align__(16) __half2 g_m[EEC * 4];       // 12.8 MB (fp16)
__device__ __align__(16) __half2 g_lf[EEC * 4];      // 12.8 MB (fp16)
__device__ __align__(16) float g_sumA[NN * CC];
__device__ __align__(16) float g_sumB[NN * CC];
__device__ __align__(16) float g_Rs[64];
__device__ float g_alpha;

// ------------------- packed f32x2 FMA ----------------------------------------
union F2 { float2 f; unsigned long long u; };

__device__ __forceinline__ void ffma2(F2& d, const F2& a, const F2& b) {
    asm("fma.rn.f32x2 %0, %1, %2, %0;" : "+l"(d.u) : "l"(a.u), "l"(b.u));
}
__device__ __forceinline__ F2 bcast2(float v) {
    F2 r; r.f = make_float2(v, v); return r;
}

// ------------------- tf32 helpers --------------------------------------------
__device__ __forceinline__ float tf32r(float x) {
    unsigned o;
    asm("cvt.rna.tf32.f32 %0, %1;" : "=r"(o) : "f"(x));
    return __uint_as_float(o);
}

// ------------------- vector reduction (atomic add, no return) -----------------
__device__ __forceinline__ void red4(float* p, float a, float b, float c, float d) {
    asm volatile("red.global.add.v4.f32 [%0], {%1, %2, %3, %4};"
                 :: "l"(p), "f"(a), "f"(b), "f"(c), "f"(d) : "memory");
}

// ------------------- generic zero --------------------------------------------
__global__ void zero4_k(float4* __restrict__ p, int n4) {
    int i = blockIdx.x * blockDim.x + threadIdx.x;
    if (i < n4) p[i] = make_float4(0.f, 0.f, 0.f, 0.f);
}

// ------------------- prep: zero deg + symmetrized R + alpha -------------------
__global__ void prep0_k(const float* __restrict__ R_raw,
                        const float* __restrict__ rsl,
                        const float* __restrict__ msg) {
    int i = blockIdx.x * blockDim.x + threadIdx.x;
    if (i < NN) g_deg[i] = 0.f;
    if (blockIdx.x == 0) {
        int t = threadIdx.x;
        if (t == 0) g_alpha = ALPHA_MAXC / (1.f + expf(-msg[0]));
        if (t < 64) {
            int c = t >> 3, d = t & 7;
            float r = 0.5f * (R_raw[c * 8 + d] + R_raw[d * 8 + c]);
            float xr = rsl[0];
            float sp = (xr > 20.f) ? xr : log1pf(expf(xr));
            g_Rs[t] = (sp + 1e-6f) * tanhf(r);
        }
    }
}

// ------------------- encoder GEMM: h = relu(x @ W1 + b1) ---------------------
// block: 128 rows x 128 cols, 256 threads, 8x8 per-thread tile (FFMA2)
__global__ __launch_bounds__(256) void enc_gemm_k(const float* __restrict__ X,
                                                  const float* __restrict__ W,
                                                  const float* __restrict__ B) {
    __shared__ float Xs[16][132];
    __shared__ float Ws[16][128];
    int tid = threadIdx.x;
    int tx = tid & 15, ty = tid >> 4;
    int row0 = blockIdx.x * 128;
    int col0 = blockIdx.y * 128;
    F2 acc[4][8];
#pragma unroll
    for (int jp = 0; jp < 4; jp++)
#pragma unroll
        for (int u = 0; u < 8; u++) acc[jp][u].f = make_float2(0.f, 0.f);

    for (int k0 = 0; k0 < INDIM; k0 += 16) {
#pragma unroll
        for (int i = 0; i < 2; i++) {
            int m = (tid >> 2) + i * 64;
            int k4 = (tid & 3) * 4;
            int gr = row0 + m;
            float4 v = make_float4(0.f, 0.f, 0.f, 0.f);
            if (gr < NN) v = *(const float4*)(X + (size_t)gr * INDIM + k0 + k4);
            Xs[k4 + 0][m] = v.x; Xs[k4 + 1][m] = v.y;
            Xs[k4 + 2][m] = v.z; Xs[k4 + 3][m] = v.w;
        }
#pragma unroll
        for (int i = 0; i < 2; i++) {
            int idx = tid + i * 256;
            int k = idx >> 5;
            int c4 = (idx & 31) * 4;
            *(float4*)&Ws[k][c4] = *(const float4*)(W + (size_t)(k0 + k) * HID + col0 + c4);
        }
        __syncthreads();
#pragma unroll
        for (int kk = 0; kk < 16; kk++) {
            F2 a2[4];
#pragma unroll
            for (int jp = 0; jp < 4; jp++)
                a2[jp].f = *(const float2*)&Xs[kk][ty * 8 + jp * 2];
            float4 wA = *(const float4*)&Ws[kk][tx * 8];
            float4 wB = *(const float4*)&Ws[kk][tx * 8 + 4];
            F2 wp[8] = {bcast2(wA.x), bcast2(wA.y), bcast2(wA.z), bcast2(wA.w),
                        bcast2(wB.x), bcast2(wB.y), bcast2(wB.z), bcast2(wB.w)};
#pragma unroll
            for (int jp = 0; jp < 4; jp++)
#pragma unroll
                for (int u = 0; u < 8; u++)
                    ffma2(acc[jp][u], a2[jp], wp[u]);
        }
        __syncthreads();
    }
    float4 bA = *(const float4*)(B + col0 + tx * 8);
    float4 bB = *(const float4*)(B + col0 + tx * 8 + 4);
#pragma unroll
    for (int jp = 0; jp < 4; jp++) {
#pragma unroll
        for (int h = 0; h < 2; h++) {
            int gr = row0 + ty * 8 + jp * 2 + h;
            if (gr < NN) {
                float4 o0, o1;
                o0.x = fmaxf((h ? acc[jp][0].f.y : acc[jp][0].f.x) + bA.x, 0.f);
                o0.y = fmaxf((h ? acc[jp][1].f.y : acc[jp][1].f.x) + bA.y, 0.f);
                o0.z = fmaxf((h ? acc[jp][2].f.y : acc[jp][2].f.x) + bA.z, 0.f);
                o0.w = fmaxf((h ? acc[jp][3].f.y : acc[jp][3].f.x) + bA.w, 0.f);
                o1.x = fmaxf((h ? acc[jp][4].f.y : acc[jp][4].f.x) + bB.x, 0.f);
                o1.y = fmaxf((h ? acc[jp][5].f.y : acc[jp][5].f.x) + bB.y, 0.f);
                o1.z = fmaxf((h ? acc[jp][6].f.y : acc[jp][6].f.x) + bB.z, 0.f);
                o1.w = fmaxf((h ? acc[jp][7].f.y : acc[jp][7].f.x) + bB.w, 0.f);
                *(float4*)(g_h + (size_t)gr * HID + col0 + tx * 8)     = o0;
                *(float4*)(g_h + (size_t)gr * HID + col0 + tx * 8 + 4) = o1;
            }
        }
    }
}

// ------------------- logits + log_softmax: one warp per node ------------------
__global__ void logits_k(const float* __restrict__ W2, const float* __restrict__ B2) {
    int gt = blockIdx.x * blockDim.x + threadIdx.x;
    int node = gt >> 5, lane = gt & 31;
    if (node >= NN) return;
    const float* hrow = g_h + (size_t)node * HID;
    float acc[8];
#pragma unroll
    for (int c = 0; c < 8; c++) acc[c] = 0.f;
    for (int j = lane; j < HID; j += 32) {
        float hv = hrow[j];
        float4 wA = *(const float4*)(W2 + j * 8);
        float4 wB = *(const float4*)(W2 + j * 8 + 4);
        acc[0] += hv * wA.x; acc[1] += hv * wA.y;
        acc[2] += hv * wA.z; acc[3] += hv * wA.w;
        acc[4] += hv * wB.x; acc[5] += hv * wB.y;
        acc[6] += hv * wB.z; acc[7] += hv * wB.w;
    }
#pragma unroll
    for (int c = 0; c < 8; c++)
#pragma unroll
        for (int off = 16; off; off >>= 1)
            acc[c] += __shfl_xor_sync(0xffffffffu, acc[c], off);
    if (lane == 0) {
        float lg[8], mx = -1e30f;
#pragma unroll
        for (int c = 0; c < 8; c++) { lg[c] = acc[c] + B2[c]; mx = fmaxf(mx, lg[c]); }
        float s = 0.f;
#pragma unroll
        for (int c = 0; c < 8; c++) s += expf(lg[c] - mx);
        float lse = mx + logf(s);
        *(float4*)(g_logphi + node * 8)     = make_float4(lg[0]-lse, lg[1]-lse, lg[2]-lse, lg[3]-lse);
        *(float4*)(g_logphi + node * 8 + 4) = make_float4(lg[4]-lse, lg[5]-lse, lg[6]-lse, lg[7]-lse);
    }
}

// ------------------- degrees -------------------------------------------------
__global__ void deg_k(const int* __restrict__ src, const int* __restrict__ dst) {
    int e = blockIdx.x * blockDim.x + threadIdx.x;
    if (e >= E2C) return;
    atomicAdd(&g_deg[src[e]], 1.f);
    atomicAdd(&g_deg[dst[e]], 1.f);
}

// ------------------- edge MLP via tf32 mma.sync (packed fragments) ------------
// block: 128 edges x 64 hidden, K=512 (P:256 | Q:256), 8 warps (4 m x 2 n)
__global__ __launch_bounds__(256) void edge_mlp_k(const int* __restrict__ src,
                                                  const int* __restrict__ dst,
                                                  const float* __restrict__ W1,
                                                  const float* __restrict__ B1,
                                                  const float* __restrict__ W2,
                                                  const float* __restrict__ B2) {
    __shared__ int   ss[128], dd[128];
    __shared__ float s0s[128], s1s[128];
    // A pack: [part][edge][k8*8 + tg*2 + pair], pair0=k(kb+tg), pair1=k(kb+tg+4); stride 40
    __shared__ float Apk[2][128][40];     // 40.96 KB
    // B pack: [part][k8][tg][2n + pair], n padded to 68 pairs (136 floats)
    __shared__ float Bpk[2][4][4][136];   // 17.4 KB
    __shared__ float Wg0[64], Wg1[64], b1s[64], w2s[64];
    __shared__ float wsum[128];

    int tid  = threadIdx.x;
    int wid  = tid >> 5;
    int lane = tid & 31;
    int gid  = lane >> 2;      // group id 0..7
    int tg   = lane & 3;       // thread-in-group 0..3
    int warp_m = wid & 3;      // 4 m-warps * 32 edges
    int warp_n = wid >> 2;     // 2 n-warps * 32 cols
    int e0 = blockIdx.x * 128;

    if (tid < 128) {
        int ge = e0 + tid;
        int s = src[ge], d = dst[ge];
        ss[tid] = s; dd[tid] = d;
        float degs = g_deg[s], degd = g_deg[d];
        float a = logf(degs + 1.f), b = logf(degd + 1.f);
        s0s[tid] = a + b; s1s[tid] = fabsf(a - b);
        float ds = fmaxf(degs, 1.f), dd2 = fmaxf(degd, 1.f);
        g_en[ge] = rsqrtf(ds * dd2);
        wsum[tid] = 0.f;
    } else {
        int t = tid - 128;
        if (t < 64) { Wg0[t] = W1[512 * 64 + t]; b1s[t] = B1[t]; }
        else { int u = t - 64; Wg1[u] = W1[513 * 64 + u]; w2s[u] = W2[u]; }
    }
    __syncthreads();

    float acc[2][4][4];
#pragma unroll
    for (int mt = 0; mt < 2; mt++)
#pragma unroll
        for (int nt = 0; nt < 4; nt++)
#pragma unroll
            for (int r = 0; r < 4; r++) acc[mt][nt][r] = 0.f;

    for (int f0 = 0; f0 < HID; f0 += 32) {
        // ---- stage A: P/Q for 128 edges x 32 feats, fragment-pair packed ----
        {
            int e = tid >> 1;
            int half = tid & 1;    // covers k8 pair {2*half, 2*half+1}
            const float4* hs4 = (const float4*)(g_h + (size_t)ss[e] * HID + f0 + half * 16);
            const float4* hd4 = (const float4*)(g_h + (size_t)dd[e] * HID + f0 + half * 16);
            float p[16], q[16];
#pragma unroll
            for (int j = 0; j < 4; j++) {
                float4 a = hs4[j];
                float4 b = hd4[j];
                p[j*4+0] = tf32r(a.x * b.x); q[j*4+0] = tf32r(fabsf(a.x - b.x));
                p[j*4+1] = tf32r(a.y * b.y); q[j*4+1] = tf32r(fabsf(a.y - b.y));
                p[j*4+2] = tf32r(a.z * b.z); q[j*4+2] = tf32r(fabsf(a.z - b.z));
                p[j*4+3] = tf32r(a.w * b.w); q[j*4+3] = tf32r(fabsf(a.w - b.w));
            }
#pragma unroll
            for (int k8l = 0; k8l < 2; k8l++) {
                int k8 = half * 2 + k8l;
                int o = k8l * 8;
                *(float4*)&Apk[0][e][k8 * 8]     = make_float4(p[o+0], p[o+4], p[o+1], p[o+5]);
                *(float4*)&Apk[0][e][k8 * 8 + 4] = make_float4(p[o+2], p[o+6], p[o+3], p[o+7]);
                *(float4*)&Apk[1][e][k8 * 8]     = make_float4(q[o+0], q[o+4], q[o+1], q[o+5]);
                *(float4*)&Apk[1][e][k8 * 8 + 4] = make_float4(q[o+2], q[o+6], q[o+3], q[o+7]);
            }
        }
        // ---- stage B: weight rows, fragment-pair packed ----
        {
            int combo = tid >> 4;          // 0..15 -> (k8, tg)
            int k8 = combo >> 2, tg2 = combo & 3;
            int n0 = (tid & 15) * 4;
            int r  = f0 + k8 * 8 + tg2;
            float4 wa  = *(const float4*)(W1 + (size_t)r * 64 + n0);
            float4 wa4 = *(const float4*)(W1 + (size_t)(r + 4) * 64 + n0);
            float4 wb  = *(const float4*)(W1 + (size_t)(256 + r) * 64 + n0);
            float4 wb4 = *(const float4*)(W1 + (size_t)(256 + r + 4) * 64 + n0);
            *(float4*)&Bpk[0][k8][tg2][2*n0]     = make_float4(tf32r(wa.x), tf32r(wa4.x), tf32r(wa.y), tf32r(wa4.y));
            *(float4*)&Bpk[0][k8][tg2][2*n0 + 4] = make_float4(tf32r(wa.z), tf32r(wa4.z), tf32r(wa.w), tf32r(wa4.w));
            *(float4*)&Bpk[1][k8][tg2][2*n0]     = make_float4(tf32r(wb.x), tf32r(wb4.x), tf32r(wb.y), tf32r(wb4.y));
            *(float4*)&Bpk[1][k8][tg2][2*n0 + 4] = make_float4(tf32r(wb.z), tf32r(wb4.z), tf32r(wb.w), tf32r(wb4.w));
        }
        __syncthreads();

        // ---- compute: 2 parts x 4 k8 steps ----
#pragma unroll
        for (int part = 0; part < 2; part++) {
#pragma unroll
            for (int k8 = 0; k8 < 4; k8++) {
                float2 bfr[4];
#pragma unroll
                for (int nt = 0; nt < 4; nt++) {
                    int n = warp_n * 32 + nt * 8 + gid;
                    bfr[nt] = *(const float2*)&Bpk[part][k8][tg][2 * n];
                }
#pragma unroll
                for (int mt = 0; mt < 2; mt++) {
                    int m = warp_m * 32 + mt * 16;
                    float2 a02 = *(const float2*)&Apk[part][m + gid][k8 * 8 + tg * 2];
                    float2 a13 = *(const float2*)&Apk[part][m + 8 + gid][k8 * 8 + tg * 2];
                    unsigned a0 = __float_as_uint(a02.x);
                    unsigned a1 = __float_as_uint(a13.x);
                    unsigned a2 = __float_as_uint(a02.y);
                    unsigned a3 = __float_as_uint(a13.y);
#pragma unroll
                    for (int nt = 0; nt < 4; nt++) {
                        asm("mma.sync.aligned.m16n8k8.row.col.f32.tf32.tf32.f32 "
                            "{%0,%1,%2,%3}, {%4,%5,%6,%7}, {%8,%9}, {%0,%1,%2,%3};"
                            : "+f"(acc[mt][nt][0]), "+f"(acc[mt][nt][1]),
                              "+f"(acc[mt][nt][2]), "+f"(acc[mt][nt][3])
                            : "r"(a0), "r"(a1), "r"(a2), "r"(a3),
                              "r"(__float_as_uint(bfr[nt].x)), "r"(__float_as_uint(bfr[nt].y)));
                    }
                }
            }
        }
        __syncthreads();
    }

    // ---- epilogue: struct feats + bias + relu + w2 dot, reduce into wsum ----
#pragma unroll
    for (int mt = 0; mt < 2; mt++) {
#pragma unroll
        for (int rh = 0; rh < 2; rh++) {
            int e = warp_m * 32 + mt * 16 + rh * 8 + gid;
            float s0 = s0s[e], s1 = s1s[e];
            float partial = 0.f;
#pragma unroll
            for (int nt = 0; nt < 4; nt++) {
#pragma unroll
                for (int cc = 0; cc < 2; cc++) {
                    int u = warp_n * 32 + nt * 8 + 2 * tg + cc;
                    float v = acc[mt][nt][rh * 2 + cc];
                    v += s0 * Wg0[u] + s1 * Wg1[u] + b1s[u];
                    v = fmaxf(v, 0.f);
                    partial += v * w2s[u];
                }
            }
            atomicAdd(&wsum[e], partial);
        }
    }
    __syncthreads();
    if (tid < 128) {
        float wr = wsum[tid] + B2[0];
        g_w[e0 + tid] = W_MAXC / (1.f + expf(-wr));
    }
}

// ------------------- fp16 row helpers ----------------------------------------
__device__ __forceinline__ void load8h(const __half2* p, float* r) {
    uint4 v = *(const uint4*)p;
    float2 f0 = __half22float2(*(__half2*)&v.x);
    float2 f1 = __half22float2(*(__half2*)&v.y);
    float2 f2 = __half22float2(*(__half2*)&v.z);
    float2 f3 = __half22float2(*(__half2*)&v.w);
    r[0]=f0.x; r[1]=f0.y; r[2]=f1.x; r[3]=f1.y;
    r[4]=f2.x; r[5]=f2.y; r[6]=f3.x; r[7]=f3.y;
}
__device__ __forceinline__ void store8h(__half2* p, const float* r) {
    uint4 v;
    __half2 h0 = __floats2half2_rn(r[0], r[1]);
    __half2 h1 = __floats2half2_rn(r[2], r[3]);
    __half2 h2 = __floats2half2_rn(r[4], r[5]);
    __half2 h3 = __floats2half2_rn(r[6], r[7]);
    v.x = *(unsigned*)&h0; v.y = *(unsigned*)&h1;
    v.z = *(unsigned*)&h2; v.w = *(unsigned*)&h3;
    *(uint4*)p = v;
}
__device__ __forceinline__ void load8(const float* p, float* r) {
    float4 v0 = *(const float4*)p;
    float4 v1 = *(const float4*)(p + 4);
    r[0]=v0.x; r[1]=v0.y; r[2]=v0.z; r[3]=v0.w;
    r[4]=v1.x; r[5]=v1.y; r[6]=v1.z; r[7]=v1.w;
}
__device__ __forceinline__ void store8(float* p, const float* r) {
    *(float4*)p       = make_float4(r[0], r[1], r[2], r[3]);
    *(float4*)(p + 4) = make_float4(r[4], r[5], r[6], r[7]);
}

// ------------------- init m = softmax(log_phi[src]) over all E edges ----------
__global__ void init_m_k(const int* __restrict__ srcAll) {
    int e = blockIdx.x * blockDim.x + threadIdx.x;
    if (e >= EEC) return;
    int s = srcAll[e];
    float lp[8];
    load8(g_logphi + s * 8, lp);
    float mx = -1e30f;
#pragma unroll
    for (int c = 0; c < 8; c++) mx = fmaxf(mx, lp[c]);
    float ex[8], sm = 0.f;
#pragma unroll
    for (int c = 0; c < 8; c++) { ex[c] = expf(lp[c] - mx); sm += ex[c]; }
    float inv = 1.f / sm;
    float o[8];
#pragma unroll
    for (int c = 0; c < 8; c++) o[c] = ex[c] * inv;
    store8h(g_m + (size_t)e * 4, o);
}

// ------------------- BP core helpers -----------------------------------------
__device__ __forceinline__ void upd_m(float* mrow, const float* lp, const float* si,
                                      const float* lf_rev, float alpha) {
    float t[8], mx = -1e30f;
#pragma unroll
    for (int c = 0; c < 8; c++) { t[c] = lp[c] + alpha * (si[c] - lf_rev[c]); mx = fmaxf(mx, t[c]); }
    float ex[8], sm = 0.f;
#pragma unroll
    for (int c = 0; c < 8; c++) { ex[c] = __expf(t[c] - mx); sm += ex[c]; }
    float inv = 1.f / sm;
    float m[8], tot = 0.f;
#pragma unroll
    for (int c = 0; c < 8; c++) {
        m[c] = (1.f - ETA_C) * mrow[c] + ETA_C * (ex[c] * inv);
        m[c] = fmaxf(m[c], EPS_C);
        tot += m[c];
    }
    float it = 1.f / tot;
#pragma unroll
    for (int c = 0; c < 8; c++) mrow[c] = m[c] * it;
}
// both directions share the kernel row: K recomputed on the fly from w, Rs
__device__ __forceinline__ void msg_lf2(const float* Rs, float w,
                                        const float* m1, const float* m2,
                                        float en, float* lf1, float* lf2) {
    float f1[8], f2[8];
#pragma unroll
    for (int c = 0; c < 8; c++) { f1[c] = 0.f; f2[c] = 0.f; }
#pragma unroll
    for (int c = 0; c < 8; c++) {
        float mc1 = m1[c], mc2 = m2[c];
#pragma unroll
        for (int d = 0; d < 8; d++) {
            float k = __expf(w * Rs[c * 8 + d]);
            f1[d] += mc1 * k;
            f2[d] += mc2 * k;
        }
    }
#pragma unroll
    for (int c = 0; c < 8; c++) {
        lf1[c] = __logf(fmaxf(f1[c], EPS_C)) * en;
        lf2[c] = __logf(fmaxf(f2[c], EPS_C)) * en;
    }
}

// ------------------- first half-iteration: lf & sum from current m ------------
__global__ __launch_bounds__(256) void iterA_k(const int* __restrict__ src,
                                               const int* __restrict__ dst,
                                               float* __restrict__ sum_w) {
    __shared__ float Rs[64];
    if (threadIdx.x < 64) Rs[threadIdx.x] = g_Rs[threadIdx.x];
    __syncthreads();
    int e = blockIdx.x * blockDim.x + threadIdx.x;
    if (e >= E2C) return;
    float w = g_w[e], en = g_en[e];
    int s = src[e], d = dst[e];
    float m1[8], m2[8], lf1[8], lf2[8];
    load8h(g_m + (size_t)e * 4, m1);
    load8h(g_m + (size_t)(e + E2C) * 4, m2);
    msg_lf2(Rs, w, m1, m2, en, lf1, lf2);
    store8h(g_lf + (size_t)e * 4, lf1);
    store8h(g_lf + (size_t)(e + E2C) * 4, lf2);
    red4(sum_w + d * 8,     lf1[0], lf1[1], lf1[2], lf1[3]);
    red4(sum_w + d * 8 + 4, lf1[4], lf1[5], lf1[6], lf1[7]);
    red4(sum_w + s * 8,     lf2[0], lf2[1], lf2[2], lf2[3]);
    red4(sum_w + s * 8 + 4, lf2[4], lf2[5], lf2[6], lf2[7]);
}

// ------------------- fused BP iteration (update m, then new lf & sum) ---------
__global__ __launch_bounds__(256) void fused_k(const int* __restrict__ src,
                                               const int* __restrict__ dst,
                                               const float* __restrict__ sum_r,
                                               float* __restrict__ sum_w) {
    __shared__ float Rs[64];
    if (threadIdx.x < 64) Rs[threadIdx.x] = g_Rs[threadIdx.x];
    __syncthreads();
    int e = blockIdx.x * blockDim.x + threadIdx.x;
    if (e >= E2C) return;
    float alpha = g_alpha;
    int s = src[e], d = dst[e];
    float lf1[8], lf2[8], m1[8], m2[8];
    load8h(g_lf + (size_t)e * 4, lf1);
    load8h(g_lf + (size_t)(e + E2C) * 4, lf2);
    load8h(g_m + (size_t)e * 4, m1);
    load8h(g_m + (size_t)(e + E2C) * 4, m2);
    {
        float lps[8], sis[8];
        load8(g_logphi + s * 8, lps);
        load8(sum_r + s * 8, sis);
        upd_m(m1, lps, sis, lf2, alpha);   // dir s->d: excl = sum[s] - lf(rev)
    }
    {
        float lpd[8], sid[8];
        load8(g_logphi + d * 8, lpd);
        load8(sum_r + d * 8, sid);
        upd_m(m2, lpd, sid, lf1, alpha);   // dir d->s: excl = sum[d] - lf1
    }
    store8h(g_m + (size_t)e * 4, m1);
    store8h(g_m + (size_t)(e + E2C) * 4, m2);
    float w = g_w[e], en = g_en[e];
    float nlf1[8], nlf2[8];
    msg_lf2(Rs, w, m1, m2, en, nlf1, nlf2);
    store8h(g_lf + (size_t)e * 4, nlf1);
    store8h(g_lf + (size_t)(e + E2C) * 4, nlf2);
    red4(sum_w + d * 8,     nlf1[0], nlf1[1], nlf1[2], nlf1[3]);
    red4(sum_w + d * 8 + 4, nlf1[4], nlf1[5], nlf1[6], nlf1[7]);
    red4(sum_w + s * 8,     nlf2[0], nlf2[1], nlf2[2], nlf2[3]);
    red4(sum_w + s * 8 + 4, nlf2[4], nlf2[5], nlf2[6], nlf2[7]);
}

// ------------------- final beliefs -------------------------------------------
__global__ void beliefs_k(const float* __restrict__ sum_r, float* __restrict__ out) {
    int n = blockIdx.x * blockDim.x + threadIdx.x;
    if (n >= NN) return;
    float alpha = g_alpha;
    float lp[8], si[8];
    load8(g_logphi + n * 8, lp);
    load8(sum_r + n * 8, si);
    float t[8], mx = -1e30f;
#pragma unroll
    for (int c = 0; c < 8; c++) { t[c] = lp[c] + alpha * si[c]; mx = fmaxf(mx, t[c]); }
    float ex[8], sm = 0.f;
#pragma unroll
    for (int c = 0; c < 8; c++) { ex[c] = expf(t[c] - mx); sm += ex[c]; }
    float inv = 1.f / sm;
    float o[8];
#pragma unroll
    for (int c = 0; c < 8; c++) o[c] = ex[c] * inv;
    store8(out + (size_t)n * 8, o);
}

// ------------------- launcher -------------------------------------------------
extern "C" void kernel_launch(void* const* d_in, const int* in_sizes, int n_in,
                              void* d_out, int out_size) {
    const float* x      = (const float*)d_in[0];
    const int*   ei     = (const int*)  d_in[1];   // [2, E] : row0 src, row1 dst
    const float* enc_w1 = (const float*)d_in[3];
    const float* enc_b1 = (const float*)d_in[4];
    const float* enc_w2 = (const float*)d_in[5];
    const float* enc_b2 = (const float*)d_in[6];
    const float* edge_w1= (const float*)d_in[7];
    const float* edge_b1= (const float*)d_in[8];
    const float* edge_w2= (const float*)d_in[9];
    const float* edge_b2= (const float*)d_in[10];
    const float* R_raw  = (const float*)d_in[11];
    const float* rsl    = (const float*)d_in[12];
    const float* msg    = (const float*)d_in[13];
    float* out = (float*)d_out;

    const int* src = ei;         // first E2 entries of row0 are unique-edge srcs
    const int* dst = ei + EEC;   // row1

    float* sumA; cudaGetSymbolAddress((void**)&sumA, g_sumA);
    float* sumB; cudaGetSymbolAddress((void**)&sumB, g_sumB);

    prep0_k<<<(NN + 255) / 256, 256>>>(R_raw, rsl, msg);
    enc_gemm_k<<<dim3((NN + 127) / 128, HID / 128), 256>>>(x, enc_w1, enc_b1);
    deg_k<<<(E2C + 255) / 256, 256>>>(src, dst);
    edge_mlp_k<<<E2C / 128, 256>>>(src, dst, edge_w1, edge_b1, edge_w2, edge_b2);
    logits_k<<<(NN * 32 + 255) / 256, 256>>>(enc_w2, enc_b2);
    init_m_k<<<(EEC + 255) / 256, 256>>>(src);  // row0 spans all E directed edges

    const int NC4 = NN * CC / 4;
    zero4_k<<<(NC4 + 255) / 256, 256>>>((float4*)sumA, NC4);
    iterA_k<<<(E2C + 255) / 256, 256>>>(src, dst, sumA);

    float* cur = sumA;
    float* nxt = sumB;
    for (int t = 0; t < T_ITERS; t++) {
        zero4_k<<<(NC4 + 255) / 256, 256>>>((float4*)nxt, NC4);
        fused_k<<<(E2C + 255) / 256, 256>>>(src, dst, cur, nxt);
        float* tmp = cur; cur = nxt; nxt = tmp;
    }
    beliefs_k<<<(NN + 255) / 256, 256>>>(cur, out);
}

// round 7
// speedup vs baseline: 1.5731x; 1.0281x over previous
#include <cuda_runtime.h>
#include <cuda_fp16.h>
#include <math.h>

#define NN      50000
#define INDIM   512
#define HID     256
#define CC      8
#define E2C     400000
#define EEC     800000
#define T_ITERS 10
#define ETA_C   0.2f
#define W_MAXC  0.8f
#define ALPHA_MAXC 1.5f
#define EPS_C   1e-12f

// ------------------- scratch (device globals; no allocation allowed) ---------
__device__ __align__(16) float g_h[NN * HID];        // 51.2 MB
__device__ __align__(16) float g_logphi[NN * CC];
__device__ __align__(16) float g_deg[NN];
__device__ __align__(16) float g_w[E2C];
__device__ __align__(16) float g_en[E2C];
__device__ __align__(16) __half2 g_m[EEC * 4];       // 12.8 MB (fp16)
__device__ __align__(16) __half2 g_lf[EEC * 4];      // 12.8 MB (fp16)
__device__ __align__(16) float g_sumA[NN * CC];
__device__ __align__(16) float g_sumB[NN * CC];
__device__ __align__(16) float g_Rs[64];
__device__ float g_alpha;

// ------------------- packed f32x2 FMA ----------------------------------------
union F2 { float2 f; unsigned long long u; };

__device__ __forceinline__ void ffma2(F2& d, const F2& a, const F2& b) {
    asm("fma.rn.f32x2 %0, %1, %2, %0;" : "+l"(d.u) : "l"(a.u), "l"(b.u));
}
__device__ __forceinline__ F2 bcast2(float v) {
    F2 r; r.f = make_float2(v, v); return r;
}

// ------------------- tf32 helpers --------------------------------------------
__device__ __forceinline__ float tf32r(float x) {
    unsigned o;
    asm("cvt.rna.tf32.f32 %0, %1;" : "=r"(o) : "f"(x));
    return __uint_as_float(o);
}

// ------------------- vector reduction (atomic add, no return) -----------------
__device__ __forceinline__ void red4(float* p, float a, float b, float c, float d) {
    asm volatile("red.global.add.v4.f32 [%0], {%1, %2, %3, %4};"
                 :: "l"(p), "f"(a), "f"(b), "f"(c), "f"(d) : "memory");
}

// ------------------- generic zero --------------------------------------------
__global__ void zero4_k(float4* __restrict__ p, int n4) {
    int i = blockIdx.x * blockDim.x + threadIdx.x;
    if (i < n4) p[i] = make_float4(0.f, 0.f, 0.f, 0.f);
}

// ------------------- prep: zero deg + symmetrized R + alpha -------------------
__global__ void prep0_k(const float* __restrict__ R_raw,
                        const float* __restrict__ rsl,
                        const float* __restrict__ msg) {
    int i = blockIdx.x * blockDim.x + threadIdx.x;
    if (i < NN) g_deg[i] = 0.f;
    if (blockIdx.x == 0) {
        int t = threadIdx.x;
        if (t == 0) g_alpha = ALPHA_MAXC / (1.f + expf(-msg[0]));
        if (t < 64) {
            int c = t >> 3, d = t & 7;
            float r = 0.5f * (R_raw[c * 8 + d] + R_raw[d * 8 + c]);
            float xr = rsl[0];
            float sp = (xr > 20.f) ? xr : log1pf(expf(xr));
            g_Rs[t] = (sp + 1e-6f) * tanhf(r);
        }
    }
}

// ------------------- encoder GEMM: h = relu(x @ W1 + b1) ---------------------
// block: 128 rows x 128 cols, 256 threads, 8x8 per-thread tile (FFMA2)
__global__ __launch_bounds__(256) void enc_gemm_k(const float* __restrict__ X,
                                                  const float* __restrict__ W,
                                                  const float* __restrict__ B) {
    __shared__ float Xs[16][132];
    __shared__ float Ws[16][128];
    int tid = threadIdx.x;
    int tx = tid & 15, ty = tid >> 4;
    int row0 = blockIdx.x * 128;
    int col0 = blockIdx.y * 128;
    F2 acc[4][8];
#pragma unroll
    for (int jp = 0; jp < 4; jp++)
#pragma unroll
        for (int u = 0; u < 8; u++) acc[jp][u].f = make_float2(0.f, 0.f);

    for (int k0 = 0; k0 < INDIM; k0 += 16) {
#pragma unroll
        for (int i = 0; i < 2; i++) {
            int m = (tid >> 2) + i * 64;
            int k4 = (tid & 3) * 4;
            int gr = row0 + m;
            float4 v = make_float4(0.f, 0.f, 0.f, 0.f);
            if (gr < NN) v = *(const float4*)(X + (size_t)gr * INDIM + k0 + k4);
            Xs[k4 + 0][m] = v.x; Xs[k4 + 1][m] = v.y;
            Xs[k4 + 2][m] = v.z; Xs[k4 + 3][m] = v.w;
        }
#pragma unroll
        for (int i = 0; i < 2; i++) {
            int idx = tid + i * 256;
            int k = idx >> 5;
            int c4 = (idx & 31) * 4;
            *(float4*)&Ws[k][c4] = *(const float4*)(W + (size_t)(k0 + k) * HID + col0 + c4);
        }
        __syncthreads();
#pragma unroll
        for (int kk = 0; kk < 16; kk++) {
            F2 a2[4];
#pragma unroll
            for (int jp = 0; jp < 4; jp++)
                a2[jp].f = *(const float2*)&Xs[kk][ty * 8 + jp * 2];
            float4 wA = *(const float4*)&Ws[kk][tx * 8];
            float4 wB = *(const float4*)&Ws[kk][tx * 8 + 4];
            F2 wp[8] = {bcast2(wA.x), bcast2(wA.y), bcast2(wA.z), bcast2(wA.w),
                        bcast2(wB.x), bcast2(wB.y), bcast2(wB.z), bcast2(wB.w)};
#pragma unroll
            for (int jp = 0; jp < 4; jp++)
#pragma unroll
                for (int u = 0; u < 8; u++)
                    ffma2(acc[jp][u], a2[jp], wp[u]);
        }
        __syncthreads();
    }
    float4 bA = *(const float4*)(B + col0 + tx * 8);
    float4 bB = *(const float4*)(B + col0 + tx * 8 + 4);
#pragma unroll
    for (int jp = 0; jp < 4; jp++) {
#pragma unroll
        for (int h = 0; h < 2; h++) {
            int gr = row0 + ty * 8 + jp * 2 + h;
            if (gr < NN) {
                float4 o0, o1;
                o0.x = fmaxf((h ? acc[jp][0].f.y : acc[jp][0].f.x) + bA.x, 0.f);
                o0.y = fmaxf((h ? acc[jp][1].f.y : acc[jp][1].f.x) + bA.y, 0.f);
                o0.z = fmaxf((h ? acc[jp][2].f.y : acc[jp][2].f.x) + bA.z, 0.f);
                o0.w = fmaxf((h ? acc[jp][3].f.y : acc[jp][3].f.x) + bA.w, 0.f);
                o1.x = fmaxf((h ? acc[jp][4].f.y : acc[jp][4].f.x) + bB.x, 0.f);
                o1.y = fmaxf((h ? acc[jp][5].f.y : acc[jp][5].f.x) + bB.y, 0.f);
                o1.z = fmaxf((h ? acc[jp][6].f.y : acc[jp][6].f.x) + bB.z, 0.f);
                o1.w = fmaxf((h ? acc[jp][7].f.y : acc[jp][7].f.x) + bB.w, 0.f);
                *(float4*)(g_h + (size_t)gr * HID + col0 + tx * 8)     = o0;
                *(float4*)(g_h + (size_t)gr * HID + col0 + tx * 8 + 4) = o1;
            }
        }
    }
}

// ------------------- logits + log_softmax: one warp per node ------------------
__global__ void logits_k(const float* __restrict__ W2, const float* __restrict__ B2) {
    int gt = blockIdx.x * blockDim.x + threadIdx.x;
    int node = gt >> 5, lane = gt & 31;
    if (node >= NN) return;
    const float* hrow = g_h + (size_t)node * HID;
    float acc[8];
#pragma unroll
    for (int c = 0; c < 8; c++) acc[c] = 0.f;
    for (int j = lane; j < HID; j += 32) {
        float hv = hrow[j];
        float4 wA = *(const float4*)(W2 + j * 8);
        float4 wB = *(const float4*)(W2 + j * 8 + 4);
        acc[0] += hv * wA.x; acc[1] += hv * wA.y;
        acc[2] += hv * wA.z; acc[3] += hv * wA.w;
        acc[4] += hv * wB.x; acc[5] += hv * wB.y;
        acc[6] += hv * wB.z; acc[7] += hv * wB.w;
    }
#pragma unroll
    for (int c = 0; c < 8; c++)
#pragma unroll
        for (int off = 16; off; off >>= 1)
            acc[c] += __shfl_xor_sync(0xffffffffu, acc[c], off);
    if (lane == 0) {
        float lg[8], mx = -1e30f;
#pragma unroll
        for (int c = 0; c < 8; c++) { lg[c] = acc[c] + B2[c]; mx = fmaxf(mx, lg[c]); }
        float s = 0.f;
#pragma unroll
        for (int c = 0; c < 8; c++) s += expf(lg[c] - mx);
        float lse = mx + logf(s);
        *(float4*)(g_logphi + node * 8)     = make_float4(lg[0]-lse, lg[1]-lse, lg[2]-lse, lg[3]-lse);
        *(float4*)(g_logphi + node * 8 + 4) = make_float4(lg[4]-lse, lg[5]-lse, lg[6]-lse, lg[7]-lse);
    }
}

// ------------------- degrees -------------------------------------------------
__global__ void deg_k(const int* __restrict__ src, const int* __restrict__ dst) {
    int e = blockIdx.x * blockDim.x + threadIdx.x;
    if (e >= E2C) return;
    atomicAdd(&g_deg[src[e]], 1.f);
    atomicAdd(&g_deg[dst[e]], 1.f);
}

// ------------------- edge MLP via tf32 mma.sync (on-the-fly P/Q) --------------
// block: 128 edges x 64 hidden, K=512 (P:256 | Q:256), 8 warps (4 m x 2 n)
// Stage raw hs/hd tiles; compute p = hs*hd, q = |hs-hd| at fragment-load time
// (one LDS pair feeds BOTH GEMM parts). HW truncation to tf32 for A operands.
__global__ __launch_bounds__(256, 3) void edge_mlp_k(const int* __restrict__ src,
                                                     const int* __restrict__ dst,
                                                     const float* __restrict__ W1,
                                                     const float* __restrict__ B1,
                                                     const float* __restrict__ W2,
                                                     const float* __restrict__ B2) {
    __shared__ int   ss[128], dd[128];
    __shared__ float s0s[128], s1s[128];
    __shared__ float Hs[128][36], Hd[128][36];   // 36.9 KB raw h tiles (32 feats)
    __shared__ float Bpk[2][4][4][136];          // 17.4 KB packed weight pairs
    __shared__ float Wg0[64], Wg1[64], b1s[64], w2s[64];
    __shared__ float wsum[128];

    int tid  = threadIdx.x;
    int wid  = tid >> 5;
    int lane = tid & 31;
    int gid  = lane >> 2;      // group id 0..7
    int tg   = lane & 3;       // thread-in-group 0..3
    int warp_m = wid & 3;      // 4 m-warps * 32 edges
    int warp_n = wid >> 2;     // 2 n-warps * 32 cols
    int e0 = blockIdx.x * 128;

    if (tid < 128) {
        int ge = e0 + tid;
        int s = src[ge], d = dst[ge];
        ss[tid] = s; dd[tid] = d;
        float degs = g_deg[s], degd = g_deg[d];
        float a = logf(degs + 1.f), b = logf(degd + 1.f);
        s0s[tid] = a + b; s1s[tid] = fabsf(a - b);
        float ds = fmaxf(degs, 1.f), dd2 = fmaxf(degd, 1.f);
        g_en[ge] = rsqrtf(ds * dd2);
        wsum[tid] = 0.f;
    } else {
        int t = tid - 128;
        if (t < 64) { Wg0[t] = W1[512 * 64 + t]; b1s[t] = B1[t]; }
        else { int u = t - 64; Wg1[u] = W1[513 * 64 + u]; w2s[u] = W2[u]; }
    }
    __syncthreads();

    float acc[2][4][4];
#pragma unroll
    for (int mt = 0; mt < 2; mt++)
#pragma unroll
        for (int nt = 0; nt < 4; nt++)
#pragma unroll
            for (int r = 0; r < 4; r++) acc[mt][nt][r] = 0.f;

    for (int f0 = 0; f0 < HID; f0 += 32) {
        // ---- stage A: raw hs/hd tiles, 128 edges x 32 feats ----
        {
            int e = tid >> 1;
            int half = tid & 1;
            const float4* hs4 = (const float4*)(g_h + (size_t)ss[e] * HID + f0 + half * 16);
            const float4* hd4 = (const float4*)(g_h + (size_t)dd[e] * HID + f0 + half * 16);
#pragma unroll
            for (int j = 0; j < 2; j++) {
                *(float4*)&Hs[e][half * 16 + j * 4] = hs4[j];
                *(float4*)&Hd[e][half * 16 + j * 4] = hd4[j];
            }
#pragma unroll
            for (int j = 2; j < 4; j++) {
                *(float4*)&Hs[e][half * 16 + j * 4] = hs4[j];
                *(float4*)&Hd[e][half * 16 + j * 4] = hd4[j];
            }
        }
        // ---- stage B: weight rows, fragment-pair packed (rows r, r+4) ----
        {
            int combo = tid >> 4;          // 0..15 -> (k8, tg)
            int k8 = combo >> 2, tg2 = combo & 3;
            int n0 = (tid & 15) * 4;
            int r  = f0 + k8 * 8 + tg2;
            float4 wa  = *(const float4*)(W1 + (size_t)r * 64 + n0);
            float4 wa4 = *(const float4*)(W1 + (size_t)(r + 4) * 64 + n0);
            float4 wb  = *(const float4*)(W1 + (size_t)(256 + r) * 64 + n0);
            float4 wb4 = *(const float4*)(W1 + (size_t)(256 + r + 4) * 64 + n0);
            *(float4*)&Bpk[0][k8][tg2][2*n0]     = make_float4(tf32r(wa.x), tf32r(wa4.x), tf32r(wa.y), tf32r(wa4.y));
            *(float4*)&Bpk[0][k8][tg2][2*n0 + 4] = make_float4(tf32r(wa.z), tf32r(wa4.z), tf32r(wa.w), tf32r(wa4.w));
            *(float4*)&Bpk[1][k8][tg2][2*n0]     = make_float4(tf32r(wb.x), tf32r(wb4.x), tf32r(wb.y), tf32r(wb4.y));
            *(float4*)&Bpk[1][k8][tg2][2*n0 + 4] = make_float4(tf32r(wb.z), tf32r(wb4.z), tf32r(wb.w), tf32r(wb4.w));
        }
        __syncthreads();

        // ---- compute: 4 k8 steps; each hs/hd LDS pair feeds both P and Q ----
#pragma unroll
        for (int k8 = 0; k8 < 4; k8++) {
            int kb = k8 * 8;
            float2 bP[4], bQ[4];
#pragma unroll
            for (int nt = 0; nt < 4; nt++) {
                int n = warp_n * 32 + nt * 8 + gid;
                bP[nt] = *(const float2*)&Bpk[0][k8][tg][2 * n];
                bQ[nt] = *(const float2*)&Bpk[1][k8][tg][2 * n];
            }
#pragma unroll
            for (int mt = 0; mt < 2; mt++) {
                int m = warp_m * 32 + mt * 16;
                float hs0 = Hs[m + gid][kb + tg];
                float hs1 = Hs[m + 8 + gid][kb + tg];
                float hs2 = Hs[m + gid][kb + 4 + tg];
                float hs3 = Hs[m + 8 + gid][kb + 4 + tg];
                float hd0 = Hd[m + gid][kb + tg];
                float hd1 = Hd[m + 8 + gid][kb + tg];
                float hd2 = Hd[m + gid][kb + 4 + tg];
                float hd3 = Hd[m + 8 + gid][kb + 4 + tg];
                unsigned p0 = __float_as_uint(hs0 * hd0);
                unsigned p1 = __float_as_uint(hs1 * hd1);
                unsigned p2 = __float_as_uint(hs2 * hd2);
                unsigned p3 = __float_as_uint(hs3 * hd3);
                unsigned q0 = __float_as_uint(fabsf(hs0 - hd0));
                unsigned q1 = __float_as_uint(fabsf(hs1 - hd1));
                unsigned q2 = __float_as_uint(fabsf(hs2 - hd2));
                unsigned q3 = __float_as_uint(fabsf(hs3 - hd3));
#pragma unroll
                for (int nt = 0; nt < 4; nt++) {
                    asm("mma.sync.aligned.m16n8k8.row.col.f32.tf32.tf32.f32 "
                        "{%0,%1,%2,%3}, {%4,%5,%6,%7}, {%8,%9}, {%0,%1,%2,%3};"
                        : "+f"(acc[mt][nt][0]), "+f"(acc[mt][nt][1]),
                          "+f"(acc[mt][nt][2]), "+f"(acc[mt][nt][3])
                        : "r"(p0), "r"(p1), "r"(p2), "r"(p3),
                          "r"(__float_as_uint(bP[nt].x)), "r"(__float_as_uint(bP[nt].y)));
                    asm("mma.sync.aligned.m16n8k8.row.col.f32.tf32.tf32.f32 "
                        "{%0,%1,%2,%3}, {%4,%5,%6,%7}, {%8,%9}, {%0,%1,%2,%3};"
                        : "+f"(acc[mt][nt][0]), "+f"(acc[mt][nt][1]),
                          "+f"(acc[mt][nt][2]), "+f"(acc[mt][nt][3])
                        : "r"(q0), "r"(q1), "r"(q2), "r"(q3),
                          "r"(__float_as_uint(bQ[nt].x)), "r"(__float_as_uint(bQ[nt].y)));
                }
            }
        }
        __syncthreads();
    }

    // ---- epilogue: struct feats + bias + relu + w2 dot, reduce into wsum ----
#pragma unroll
    for (int mt = 0; mt < 2; mt++) {
#pragma unroll
        for (int rh = 0; rh < 2; rh++) {
            int e = warp_m * 32 + mt * 16 + rh * 8 + gid;
            float s0 = s0s[e], s1 = s1s[e];
            float partial = 0.f;
#pragma unroll
            for (int nt = 0; nt < 4; nt++) {
#pragma unroll
                for (int cc = 0; cc < 2; cc++) {
                    int u = warp_n * 32 + nt * 8 + 2 * tg + cc;
                    float v = acc[mt][nt][rh * 2 + cc];
                    v += s0 * Wg0[u] + s1 * Wg1[u] + b1s[u];
                    v = fmaxf(v, 0.f);
                    partial += v * w2s[u];
                }
            }
            atomicAdd(&wsum[e], partial);
        }
    }
    __syncthreads();
    if (tid < 128) {
        float wr = wsum[tid] + B2[0];
        g_w[e0 + tid] = W_MAXC / (1.f + expf(-wr));
    }
}

// ------------------- fp16 row helpers ----------------------------------------
__device__ __forceinline__ void load8h(const __half2* p, float* r) {
    uint4 v = *(const uint4*)p;
    float2 f0 = __half22float2(*(__half2*)&v.x);
    float2 f1 = __half22float2(*(__half2*)&v.y);
    float2 f2 = __half22float2(*(__half2*)&v.z);
    float2 f3 = __half22float2(*(__half2*)&v.w);
    r[0]=f0.x; r[1]=f0.y; r[2]=f1.x; r[3]=f1.y;
    r[4]=f2.x; r[5]=f2.y; r[6]=f3.x; r[7]=f3.y;
}
__device__ __forceinline__ void store8h(__half2* p, const float* r) {
    uint4 v;
    __half2 h0 = __floats2half2_rn(r[0], r[1]);
    __half2 h1 = __floats2half2_rn(r[2], r[3]);
    __half2 h2 = __floats2half2_rn(r[4], r[5]);
    __half2 h3 = __floats2half2_rn(r[6], r[7]);
    v.x = *(unsigned*)&h0; v.y = *(unsigned*)&h1;
    v.z = *(unsigned*)&h2; v.w = *(unsigned*)&h3;
    *(uint4*)p = v;
}
__device__ __forceinline__ void load8(const float* p, float* r) {
    float4 v0 = *(const float4*)p;
    float4 v1 = *(const float4*)(p + 4);
    r[0]=v0.x; r[1]=v0.y; r[2]=v0.z; r[3]=v0.w;
    r[4]=v1.x; r[5]=v1.y; r[6]=v1.z; r[7]=v1.w;
}
__device__ __forceinline__ void store8(float* p, const float* r) {
    *(float4*)p       = make_float4(r[0], r[1], r[2], r[3]);
    *(float4*)(p + 4) = make_float4(r[4], r[5], r[6], r[7]);
}

// ------------------- init m = softmax(log_phi[src]) over all E edges ----------
__global__ void init_m_k(const int* __restrict__ srcAll) {
    int e = blockIdx.x * blockDim.x + threadIdx.x;
    if (e >= EEC) return;
    int s = srcAll[e];
    float lp[8];
    load8(g_logphi + s * 8, lp);
    float mx = -1e30f;
#pragma unroll
    for (int c = 0; c < 8; c++) mx = fmaxf(mx, lp[c]);
    float ex[8], sm = 0.f;
#pragma unroll
    for (int c = 0; c < 8; c++) { ex[c] = expf(lp[c] - mx); sm += ex[c]; }
    float inv = 1.f / sm;
    float o[8];
#pragma unroll
    for (int c = 0; c < 8; c++) o[c] = ex[c] * inv;
    store8h(g_m + (size_t)e * 4, o);
}

// ------------------- BP core helpers -----------------------------------------
__device__ __forceinline__ void upd_m(float* mrow, const float* lp, const float* si,
                                      const float* lf_rev, float alpha) {
    float t[8], mx = -1e30f;
#pragma unroll
    for (int c = 0; c < 8; c++) { t[c] = lp[c] + alpha * (si[c] - lf_rev[c]); mx = fmaxf(mx, t[c]); }
    float ex[8], sm = 0.f;
#pragma unroll
    for (int c = 0; c < 8; c++) { ex[c] = __expf(t[c] - mx); sm += ex[c]; }
    float inv = 1.f / sm;
    float m[8], tot = 0.f;
#pragma unroll
    for (int c = 0; c < 8; c++) {
        m[c] = (1.f - ETA_C) * mrow[c] + ETA_C * (ex[c] * inv);
        m[c] = fmaxf(m[c], EPS_C);
        tot += m[c];
    }
    float it = 1.f / tot;
#pragma unroll
    for (int c = 0; c < 8; c++) mrow[c] = m[c] * it;
}
// both directions share the kernel row: K recomputed on the fly from w, Rs
__device__ __forceinline__ void msg_lf2(const float* Rs, float w,
                                        const float* m1, const float* m2,
                                        float en, float* lf1, float* lf2) {
    float f1[8], f2[8];
#pragma unroll
    for (int c = 0; c < 8; c++) { f1[c] = 0.f; f2[c] = 0.f; }
#pragma unroll
    for (int c = 0; c < 8; c++) {
        float mc1 = m1[c], mc2 = m2[c];
#pragma unroll
        for (int d = 0; d < 8; d++) {
            float k = __expf(w * Rs[c * 8 + d]);
            f1[d] += mc1 * k;
            f2[d] += mc2 * k;
        }
    }
#pragma unroll
    for (int c = 0; c < 8; c++) {
        lf1[c] = __logf(fmaxf(f1[c], EPS_C)) * en;
        lf2[c] = __logf(fmaxf(f2[c], EPS_C)) * en;
    }
}

// ------------------- first half-iteration: lf & sum from current m ------------
__global__ __launch_bounds__(256) void iterA_k(const int* __restrict__ src,
                                               const int* __restrict__ dst,
                                               float* __restrict__ sum_w) {
    __shared__ float Rs[64];
    if (threadIdx.x < 64) Rs[threadIdx.x] = g_Rs[threadIdx.x];
    __syncthreads();
    int e = blockIdx.x * blockDim.x + threadIdx.x;
    if (e >= E2C) return;
    float w = g_w[e], en = g_en[e];
    int s = src[e], d = dst[e];
    float m1[8], m2[8], lf1[8], lf2[8];
    load8h(g_m + (size_t)e * 4, m1);
    load8h(g_m + (size_t)(e + E2C) * 4, m2);
    msg_lf2(Rs, w, m1, m2, en, lf1, lf2);
    store8h(g_lf + (size_t)e * 4, lf1);
    store8h(g_lf + (size_t)(e + E2C) * 4, lf2);
    red4(sum_w + d * 8,     lf1[0], lf1[1], lf1[2], lf1[3]);
    red4(sum_w + d * 8 + 4, lf1[4], lf1[5], lf1[6], lf1[7]);
    red4(sum_w + s * 8,     lf2[0], lf2[1], lf2[2], lf2[3]);
    red4(sum_w + s * 8 + 4, lf2[4], lf2[5], lf2[6], lf2[7]);
}

// ------------------- fused BP iteration (update m, then new lf & sum) ---------
__global__ __launch_bounds__(256) void fused_k(const int* __restrict__ src,
                                               const int* __restrict__ dst,
                                               const float* __restrict__ sum_r,
                                               float* __restrict__ sum_w) {
    __shared__ float Rs[64];
    if (threadIdx.x < 64) Rs[threadIdx.x] = g_Rs[threadIdx.x];
    __syncthreads();
    int e = blockIdx.x * blockDim.x + threadIdx.x;
    if (e >= E2C) return;
    float alpha = g_alpha;
    int s = src[e], d = dst[e];
    float lf1[8], lf2[8], m1[8], m2[8];
    load8h(g_lf + (size_t)e * 4, lf1);
    load8h(g_lf + (size_t)(e + E2C) * 4, lf2);
    load8h(g_m + (size_t)e * 4, m1);
    load8h(g_m + (size_t)(e + E2C) * 4, m2);
    {
        float lps[8], sis[8];
        load8(g_logphi + s * 8, lps);
        load8(sum_r + s * 8, sis);
        upd_m(m1, lps, sis, lf2, alpha);   // dir s->d: excl = sum[s] - lf(rev)
    }
    {
        float lpd[8], sid[8];
        load8(g_logphi + d * 8, lpd);
        load8(sum_r + d * 8, sid);
        upd_m(m2, lpd, sid, lf1, alpha);   // dir d->s: excl = sum[d] - lf1
    }
    store8h(g_m + (size_t)e * 4, m1);
    store8h(g_m + (size_t)(e + E2C) * 4, m2);
    float w = g_w[e], en = g_en[e];
    float nlf1[8], nlf2[8];
    msg_lf2(Rs, w, m1, m2, en, nlf1, nlf2);
    store8h(g_lf + (size_t)e * 4, nlf1);
    store8h(g_lf + (size_t)(e + E2C) * 4, nlf2);
    red4(sum_w + d * 8,     nlf1[0], nlf1[1], nlf1[2], nlf1[3]);
    red4(sum_w + d * 8 + 4, nlf1[4], nlf1[5], nlf1[6], nlf1[7]);
    red4(sum_w + s * 8,     nlf2[0], nlf2[1], nlf2[2], nlf2[3]);
    red4(sum_w + s * 8 + 4, nlf2[4], nlf2[5], nlf2[6], nlf2[7]);
}

// ------------------- final beliefs -------------------------------------------
__global__ void beliefs_k(const float* __restrict__ sum_r, float* __restrict__ out) {
    int n = blockIdx.x * blockDim.x + threadIdx.x;
    if (n >= NN) return;
    float alpha = g_alpha;
    float lp[8], si[8];
    load8(g_logphi + n * 8, lp);
    load8(sum_r + n * 8, si);
    float t[8], mx = -1e30f;
#pragma unroll
    for (int c = 0; c < 8; c++) { t[c] = lp[c] + alpha * si[c]; mx = fmaxf(mx, t[c]); }
    float ex[8], sm = 0.f;
#pragma unroll
    for (int c = 0; c < 8; c++) { ex[c] = expf(t[c] - mx); sm += ex[c]; }
    float inv = 1.f / sm;
    float o[8];
#pragma unroll
    for (int c = 0; c < 8; c++) o[c] = ex[c] * inv;
    store8(out + (size_t)n * 8, o);
}

// ------------------- launcher -------------------------------------------------
extern "C" void kernel_launch(void* const* d_in, const int* in_sizes, int n_in,
                              void* d_out, int out_size) {
    const float* x      = (const float*)d_in[0];
    const int*   ei     = (const int*)  d_in[1];   // [2, E] : row0 src, row1 dst
    const float* enc_w1 = (const float*)d_in[3];
    const float* enc_b1 = (const float*)d_in[4];
    const float* enc_w2 = (const float*)d_in[5];
    const float* enc_b2 = (const float*)d_in[6];
    const float* edge_w1= (const float*)d_in[7];
    const float* edge_b1= (const float*)d_in[8];
    const float* edge_w2= (const float*)d_in[9];
    const float* edge_b2= (const float*)d_in[10];
    const float* R_raw  = (const float*)d_in[11];
    const float* rsl    = (const float*)d_in[12];
    const float* msg    = (const float*)d_in[13];
    float* out = (float*)d_out;

    const int* src = ei;         // first E2 entries of row0 are unique-edge srcs
    const int* dst = ei + EEC;   // row1

    float* sumA; cudaGetSymbolAddress((void**)&sumA, g_sumA);
    float* sumB; cudaGetSymbolAddress((void**)&sumB, g_sumB);

    prep0_k<<<(NN + 255) / 256, 256>>>(R_raw, rsl, msg);
    enc_gemm_k<<<dim3((NN + 127) / 128, HID / 128), 256>>>(x, enc_w1, enc_b1);
    deg_k<<<(E2C + 255) / 256, 256>>>(src, dst);
    edge_mlp_k<<<E2C / 128, 256>>>(src, dst, edge_w1, edge_b1, edge_w2, edge_b2);
    logits_k<<<(NN * 32 + 255) / 256, 256>>>(enc_w2, enc_b2);
    init_m_k<<<(EEC + 255) / 256, 256>>>(src);  // row0 spans all E directed edges

    const int NC4 = NN * CC / 4;
    zero4_k<<<(NC4 + 255) / 256, 256>>>((float4*)sumA, NC4);
    iterA_k<<<(E2C + 255) / 256, 256>>>(src, dst, sumA);

    float* cur = sumA;
    float* nxt = sumB;
    for (int t = 0; t < T_ITERS; t++) {
        zero4_k<<<(NC4 + 255) / 256, 256>>>((float4*)nxt, NC4);
        fused_k<<<(E2C + 255) / 256, 256>>>(src, dst, cur, nxt);
        float* tmp = cur; cur = nxt; nxt = tmp;
    }
    beliefs_k<<<(NN + 255) / 256, 256>>>(cur, out);
}